// round 13
// baseline (speedup 1.0000x reference)
#include <cuda_runtime.h>
#include <cuda_bf16.h>
#include <cstdint>
#include <math.h>

#define N_NODES 50000
#define E_MAX   800000
#define DIN     128
#define DH      256
#define DOUT    64
#define LAYERS  4

#define SCAN_NB  ((N_NODES + 1023) / 1024)   // 49

// ---------------- device scratch (allocation-free) ----------------
__device__ float g_dinv[N_NODES];
__device__ int   g_cnt[N_NODES];
__device__ int   g_partial[64];
__device__ int   g_rowptr[N_NODES + 1];
__device__ int   g_cursor[N_NODES];
__device__ int2  g_csr[E_MAX];                    // {src, norm-as-int}
__device__ __nv_bfloat16 g_xhi[(size_t)N_NODES * DIN];
__device__ __nv_bfloat16 g_xlo[(size_t)N_NODES * DIN];
__device__ __nv_bfloat16 g_hhiA[(size_t)N_NODES * DH];
__device__ __nv_bfloat16 g_hloA[(size_t)N_NODES * DH];
__device__ __nv_bfloat16 g_hhiB[(size_t)N_NODES * DH];
__device__ __nv_bfloat16 g_hloB[(size_t)N_NODES * DH];
// transposed bf16 weights [N][K] (K-major rows)
__device__ __nv_bfloat16 g_wembh[DH * DIN], g_wembl[DH * DIN];
__device__ __nv_bfloat16 g_wconvh[LAYERS * DH * DH], g_wconvl[LAYERS * DH * DH];
__device__ __nv_bfloat16 g_wouth[DOUT * DH], g_woutl[DOUT * DH];

// ---------------- CSR build ----------------
__global__ void k_zero(int* cnt, int n) {
    int i = blockIdx.x * blockDim.x + threadIdx.x;
    if (i < n) cnt[i] = 0;
}
__global__ void k_count(const int* __restrict__ dst, int* cnt, int E) {
    int e = blockIdx.x * blockDim.x + threadIdx.x;
    if (e < E) atomicAdd(&cnt[dst[e]], 1);
}
__global__ void k_dinv(const int* __restrict__ cnt, float* dinv, int n) {
    int i = blockIdx.x * blockDim.x + threadIdx.x;
    if (i < n) dinv[i] = rsqrtf((float)cnt[i] + 1.0f);   // +1 self-loop
}
__global__ void k_scan1(const int* __restrict__ cnt, int* partial, int n) {
    __shared__ int sd[256];
    int base = blockIdx.x * 1024;
    int t = threadIdx.x;
    int s = 0;
    #pragma unroll
    for (int i = 0; i < 4; i++) {
        int idx = base + t + i * 256;
        if (idx < n) s += cnt[idx];
    }
    sd[t] = s;
    __syncthreads();
    #pragma unroll
    for (int off = 128; off > 0; off >>= 1) {
        if (t < off) sd[t] += sd[t + off];
        __syncthreads();
    }
    if (t == 0) partial[blockIdx.x] = sd[0];
}
__global__ void k_scan2(int* partial, int* rowptr, int nb, int n) {
    __shared__ int sh[64];
    int t = threadIdx.x;
    int v = (t < nb) ? partial[t] : 0;
    sh[t] = v;
    __syncthreads();
    #pragma unroll
    for (int off = 1; off < 64; off <<= 1) {
        int x = (t >= off) ? sh[t - off] : 0;
        __syncthreads();
        sh[t] += x;
        __syncthreads();
    }
    if (t < nb) partial[t] = sh[t] - v;
    if (t == 63) rowptr[n] = sh[63];
}
__global__ void k_scan3(const int* __restrict__ cnt, const int* __restrict__ partial,
                        int* rowptr, int* cursor, int n) {
    __shared__ int sh[256];
    int base = blockIdx.x * 1024;
    int t = threadIdx.x;
    int i0 = base + t * 4;
    int c0 = (i0     < n) ? cnt[i0    ] : 0;
    int c1 = (i0 + 1 < n) ? cnt[i0 + 1] : 0;
    int c2 = (i0 + 2 < n) ? cnt[i0 + 2] : 0;
    int c3 = (i0 + 3 < n) ? cnt[i0 + 3] : 0;
    int tot = c0 + c1 + c2 + c3;
    sh[t] = tot;
    __syncthreads();
    #pragma unroll
    for (int off = 1; off < 256; off <<= 1) {
        int x = (t >= off) ? sh[t - off] : 0;
        __syncthreads();
        sh[t] += x;
        __syncthreads();
    }
    int run = sh[t] - tot + partial[blockIdx.x];
    if (i0     < n) { rowptr[i0    ] = run; cursor[i0    ] = run; run += c0; }
    if (i0 + 1 < n) { rowptr[i0 + 1] = run; cursor[i0 + 1] = run; run += c1; }
    if (i0 + 2 < n) { rowptr[i0 + 2] = run; cursor[i0 + 2] = run; run += c2; }
    if (i0 + 3 < n) { rowptr[i0 + 3] = run; cursor[i0 + 3] = run; }
}
__global__ void k_fill(const int* __restrict__ src, const int* __restrict__ dst,
                       const float* __restrict__ dinv, int* cursor,
                       int2* __restrict__ csr, int E) {
    int e = blockIdx.x * blockDim.x + threadIdx.x;
    if (e >= E) return;
    int s = src[e], d = dst[e];
    int pos = atomicAdd(&cursor[d], 1);
    float w = dinv[s] * dinv[d];
    csr[pos] = make_int2(s, __float_as_int(w));
}

// ---------------- conversions ----------------
__device__ __forceinline__ void split_bf16(float v, __nv_bfloat16& hi, __nv_bfloat16& lo) {
    hi = __float2bfloat16_rn(v);
    lo = __float2bfloat16_rn(v - __bfloat162float(hi));
}
__global__ void k_conv_x(const float* __restrict__ x,
                         __nv_bfloat16* __restrict__ hi, __nv_bfloat16* __restrict__ lo,
                         int total) {
    int i = blockIdx.x * blockDim.x + threadIdx.x;
    if (i >= total) return;
    split_bf16(x[i], hi[i], lo[i]);
}
__global__ void k_conv_w(const float* __restrict__ W,
                         __nv_bfloat16* __restrict__ hi, __nv_bfloat16* __restrict__ lo,
                         int K, int N) {
    int i = blockIdx.x * blockDim.x + threadIdx.x;
    if (i >= K * N) return;
    int k = i / N, n = i % N;
    __nv_bfloat16 h, l;
    split_bf16(W[i], h, l);
    hi[(size_t)n * K + k] = h;
    lo[(size_t)n * K + k] = l;
}

// ---------------- PTX helpers ----------------
__device__ __forceinline__ void mma16816(float* c, const uint32_t* a, const uint32_t* b) {
    asm volatile(
        "mma.sync.aligned.m16n8k16.row.col.f32.bf16.bf16.f32 "
        "{%0,%1,%2,%3}, {%4,%5,%6,%7}, {%8,%9}, {%0,%1,%2,%3};"
        : "+f"(c[0]), "+f"(c[1]), "+f"(c[2]), "+f"(c[3])
        : "r"(a[0]), "r"(a[1]), "r"(a[2]), "r"(a[3]), "r"(b[0]), "r"(b[1]));
}
__device__ __forceinline__ void cp16(uint32_t dst, const void* src) {
    asm volatile("cp.async.cg.shared.global [%0], [%1], 16;"
                 :: "r"(dst), "l"(src) : "memory");
}
__device__ __forceinline__ void cp16p(uint32_t dst, const void* src, bool valid) {
    int sz = valid ? 16 : 0;
    asm volatile("cp.async.cg.shared.global [%0], [%1], 16, %2;"
                 :: "r"(dst), "l"(src), "r"(sz) : "memory");
}
__device__ __forceinline__ void ldsm4(uint32_t* r, uint32_t addr) {
    asm volatile("ldmatrix.sync.aligned.m8n8.x4.shared.b16 {%0,%1,%2,%3}, [%4];"
                 : "=r"(r[0]), "=r"(r[1]), "=r"(r[2]), "=r"(r[3]) : "r"(addr));
}

// =====================================================================
// Fused layer kernel: h_out = tanh((S . h_in) @ W^T + b)
// CTA = 64 nodes. Phase 1: gather agg rows into swizzled smem (bf16 split).
// Phase 2: 3-term compensated mma.sync GEMM over all 256 output cols.
// Smem: AsH 64x512B swizzled (32KB) | AsL (32KB) | B 2 stages x 24KB = 112KB
// =====================================================================
#define L_OFF_AL  32768
#define L_OFF_B   65536
#define L_BSTAGE  24576
#define L_BLO     12288
#define L_SMEM    (L_OFF_B + 2 * L_BSTAGE)     // 114688
#define NCHUNK    (DH / 16)                    // 16

__device__ __forceinline__ uint32_t a_swz(uint32_t base, int row, int colByte) {
    return base + row * 512 + (colByte ^ ((row & 7) << 4));
}

__global__ __launch_bounds__(256, 2)
void k_layer(const __nv_bfloat16* __restrict__ inHi, const __nv_bfloat16* __restrict__ inLo,
             const int2* __restrict__ csr, const int* __restrict__ rowptr,
             const float* __restrict__ dinv,
             const __nv_bfloat16* __restrict__ Bhi, const __nv_bfloat16* __restrict__ Blo,
             const float* __restrict__ bias,
             __nv_bfloat16* __restrict__ outHi, __nv_bfloat16* __restrict__ outLo,
             int n) {
    extern __shared__ char smem[];
    uint32_t sbase = (uint32_t)__cvta_generic_to_shared(smem);
    int tid = threadIdx.x;
    int lane = tid & 31, wid = tid >> 5;
    int row0 = blockIdx.x * 64;

    // ---- prologue: start B chunks 0,1 (overlaps with gather) ----
    {
        int r = tid;   // 0..255 = N row
        #pragma unroll
        for (int c = 0; c < 2; c++) {
            uint32_t bb = sbase + L_OFF_B + c * L_BSTAGE;
            const __nv_bfloat16* pH = Bhi + (size_t)r * DH + c * 16;
            const __nv_bfloat16* pL = Blo + (size_t)r * DH + c * 16;
            cp16(bb + r * 48,              pH);
            cp16(bb + r * 48 + 16,         pH + 8);
            cp16(bb + L_BLO + r * 48,      pL);
            cp16(bb + L_BLO + r * 48 + 16, pL + 8);
            asm volatile("cp.async.commit_group;" ::: "memory");
        }
    }

    // ---- phase 1: gather 8 nodes per warp into A smem ----
    for (int q = 0; q < 8; q++) {
        int r = wid * 8 + q;          // local row 0..63
        int i = row0 + r;
        float acc[8];
        #pragma unroll
        for (int z = 0; z < 8; z++) acc[z] = 0.f;

        if (i < n) {
            float di = dinv[i];
            float w0 = di * di;
            {
                uint4 vh = *reinterpret_cast<const uint4*>(inHi + (size_t)i * DH + lane * 8);
                uint4 vl = *reinterpret_cast<const uint4*>(inLo + (size_t)i * DH + lane * 8);
                const uint32_t* ph = reinterpret_cast<const uint32_t*>(&vh);
                const uint32_t* pl = reinterpret_cast<const uint32_t*>(&vl);
                #pragma unroll
                for (int z = 0; z < 4; z++) {
                    float2 h2 = __bfloat1622float2(*reinterpret_cast<const __nv_bfloat162*>(&ph[z]));
                    float2 l2 = __bfloat1622float2(*reinterpret_cast<const __nv_bfloat162*>(&pl[z]));
                    acc[z*2]   += w0 * (h2.x + l2.x);
                    acc[z*2+1] += w0 * (h2.y + l2.y);
                }
            }
            int beg = rowptr[i], end = rowptr[i + 1];
            int j = beg;
            for (; j + 1 < end; j += 2) {
                int2 e0 = csr[j], e1 = csr[j + 1];
                float wa = __int_as_float(e0.y), wb = __int_as_float(e1.y);
                uint4 ah4 = *reinterpret_cast<const uint4*>(inHi + (size_t)e0.x * DH + lane * 8);
                uint4 al4 = *reinterpret_cast<const uint4*>(inLo + (size_t)e0.x * DH + lane * 8);
                uint4 bh4 = *reinterpret_cast<const uint4*>(inHi + (size_t)e1.x * DH + lane * 8);
                uint4 bl4 = *reinterpret_cast<const uint4*>(inLo + (size_t)e1.x * DH + lane * 8);
                const uint32_t* p0h = reinterpret_cast<const uint32_t*>(&ah4);
                const uint32_t* p0l = reinterpret_cast<const uint32_t*>(&al4);
                const uint32_t* p1h = reinterpret_cast<const uint32_t*>(&bh4);
                const uint32_t* p1l = reinterpret_cast<const uint32_t*>(&bl4);
                #pragma unroll
                for (int z = 0; z < 4; z++) {
                    float2 h0 = __bfloat1622float2(*reinterpret_cast<const __nv_bfloat162*>(&p0h[z]));
                    float2 l0 = __bfloat1622float2(*reinterpret_cast<const __nv_bfloat162*>(&p0l[z]));
                    float2 h1 = __bfloat1622float2(*reinterpret_cast<const __nv_bfloat162*>(&p1h[z]));
                    float2 l1 = __bfloat1622float2(*reinterpret_cast<const __nv_bfloat162*>(&p1l[z]));
                    acc[z*2]   += wa * (h0.x + l0.x) + wb * (h1.x + l1.x);
                    acc[z*2+1] += wa * (h0.y + l0.y) + wb * (h1.y + l1.y);
                }
            }
            if (j < end) {
                int2 e0 = csr[j];
                float wa = __int_as_float(e0.y);
                uint4 ah4 = *reinterpret_cast<const uint4*>(inHi + (size_t)e0.x * DH + lane * 8);
                uint4 al4 = *reinterpret_cast<const uint4*>(inLo + (size_t)e0.x * DH + lane * 8);
                const uint32_t* p0h = reinterpret_cast<const uint32_t*>(&ah4);
                const uint32_t* p0l = reinterpret_cast<const uint32_t*>(&al4);
                #pragma unroll
                for (int z = 0; z < 4; z++) {
                    float2 h0 = __bfloat1622float2(*reinterpret_cast<const __nv_bfloat162*>(&p0h[z]));
                    float2 l0 = __bfloat1622float2(*reinterpret_cast<const __nv_bfloat162*>(&p0l[z]));
                    acc[z*2]   += wa * (h0.x + l0.x);
                    acc[z*2+1] += wa * (h0.y + l0.y);
                }
            }
        }

        // split -> smem (swizzled)
        uint32_t hp[4], lp[4];
        #pragma unroll
        for (int z = 0; z < 4; z++) {
            __nv_bfloat16 h0, l0, h1, l1;
            split_bf16(acc[z*2],   h0, l0);
            split_bf16(acc[z*2+1], h1, l1);
            __nv_bfloat162 ph; ph.x = h0; ph.y = h1;
            __nv_bfloat162 pl; pl.x = l0; pl.y = l1;
            hp[z] = *reinterpret_cast<uint32_t*>(&ph);
            lp[z] = *reinterpret_cast<uint32_t*>(&pl);
        }
        uint32_t adH = a_swz(sbase,            r, lane * 16);
        uint32_t adL = a_swz(sbase + L_OFF_AL, r, lane * 16);
        asm volatile("st.shared.v4.b32 [%0], {%1,%2,%3,%4};"
                     :: "r"(adH), "r"(hp[0]), "r"(hp[1]), "r"(hp[2]), "r"(hp[3]) : "memory");
        asm volatile("st.shared.v4.b32 [%0], {%1,%2,%3,%4};"
                     :: "r"(adL), "r"(lp[0]), "r"(lp[1]), "r"(lp[2]), "r"(lp[3]) : "memory");
    }
    __syncthreads();

    // ---- phase 2: GEMM 64x256x256, 3-term ----
    int wm = wid & 1;              // 2 m-groups of 32 rows
    int wn = wid >> 1;             // 4 n-groups of 64 cols
    int g = lane >> 2, t2 = (lane & 3) * 2;
    int b_r = (lane & 7) + ((lane >> 4) & 1) * 8;
    int b_kB = ((lane >> 3) & 1) * 16;

    float acc[2][8][4];
    #pragma unroll
    for (int mt = 0; mt < 2; mt++)
        #pragma unroll
        for (int nt = 0; nt < 8; nt++)
            #pragma unroll
            for (int z = 0; z < 4; z++) acc[mt][nt][z] = 0.f;

    for (int c = 0; c < NCHUNK; c++) {
        if (c + 1 < NCHUNK) asm volatile("cp.async.wait_group 1;" ::: "memory");
        else                asm volatile("cp.async.wait_group 0;" ::: "memory");
        __syncthreads();

        uint32_t bb = sbase + L_OFF_B + (c & 1) * L_BSTAGE;

        // A fragments for this k16
        uint32_t ah[2][4], al[2][4];
        #pragma unroll
        for (int mt = 0; mt < 2; mt++) {
            int row = wm * 32 + mt * 16 + (lane & 15);
            int colB = c * 32 + (lane >> 4) * 16;
            ldsm4(ah[mt], a_swz(sbase,            row, colB));
            ldsm4(al[mt], a_swz(sbase + L_OFF_AL, row, colB));
        }

        #pragma unroll
        for (int h = 0; h < 2; h++) {
            uint32_t bh[4][2], bl[4][2];
            #pragma unroll
            for (int np = 0; np < 4; np += 2) {
                int nb = wn * 64 + h * 32 + np * 8;
                uint32_t r4[4];
                ldsm4(r4, bb + (nb + b_r) * 48 + b_kB);
                bh[np][0] = r4[0]; bh[np][1] = r4[1];
                bh[np+1][0] = r4[2]; bh[np+1][1] = r4[3];
                ldsm4(r4, bb + L_BLO + (nb + b_r) * 48 + b_kB);
                bl[np][0] = r4[0]; bl[np][1] = r4[1];
                bl[np+1][0] = r4[2]; bl[np+1][1] = r4[3];
            }
            #pragma unroll
            for (int mt = 0; mt < 2; mt++)
                #pragma unroll
                for (int nt = 0; nt < 4; nt++) {
                    mma16816(acc[mt][h*4+nt], ah[mt], bh[nt]);
                    mma16816(acc[mt][h*4+nt], ah[mt], bl[nt]);
                    mma16816(acc[mt][h*4+nt], al[mt], bh[nt]);
                }
        }
        __syncthreads();

        if (c + 2 < NCHUNK) {
            int r = tid;
            uint32_t nb2 = sbase + L_OFF_B + (c & 1) * L_BSTAGE;
            const __nv_bfloat16* pH = Bhi + (size_t)r * DH + (c + 2) * 16;
            const __nv_bfloat16* pL = Blo + (size_t)r * DH + (c + 2) * 16;
            cp16(nb2 + r * 48,              pH);
            cp16(nb2 + r * 48 + 16,         pH + 8);
            cp16(nb2 + L_BLO + r * 48,      pL);
            cp16(nb2 + L_BLO + r * 48 + 16, pL + 8);
            asm volatile("cp.async.commit_group;" ::: "memory");
        }
    }

    // ---- epilogue: tanh(v + bias) -> bf16 split ----
    #pragma unroll
    for (int mt = 0; mt < 2; mt++) {
        #pragma unroll
        for (int half = 0; half < 2; half++) {
            int r = row0 + wm * 32 + mt * 16 + g + half * 8;
            if (r >= n) continue;
            #pragma unroll
            for (int nt = 0; nt < 8; nt++) {
                int col = wn * 64 + (nt >> 2) * 32 + (nt & 3) * 8 + t2;
                float v0 = tanhf(acc[mt][nt][half*2+0] + bias[col]);
                float v1 = tanhf(acc[mt][nt][half*2+1] + bias[col+1]);
                __nv_bfloat16 h0, l0, h1, l1;
                split_bf16(v0, h0, l0);
                split_bf16(v1, h1, l1);
                __nv_bfloat162 ph; ph.x = h0; ph.y = h1;
                __nv_bfloat162 pl; pl.x = l0; pl.y = l1;
                *reinterpret_cast<__nv_bfloat162*>(&outHi[(size_t)r * DH + col]) = ph;
                *reinterpret_cast<__nv_bfloat162*>(&outLo[(size_t)r * DH + col]) = pl;
            }
        }
    }
}

// ---------------- standalone GEMM (emb / out), cp.async 3-stage ----------------
#define LDSW  40
#define ST_AH 0
#define ST_AL (128 * LDSW)
#define ST_BH (2 * 128 * LDSW)
#define ST_BL (2 * 128 * LDSW + 64 * LDSW)
#define STAGE (2 * 128 * LDSW + 2 * 64 * LDSW)
#define NSTG  3

template<int KTOT, int EPI>   // EPI: 0 = bias + bf16 split out, 2 = bias + fp32 out
__global__ __launch_bounds__(256)
void k_mma_gemm(const __nv_bfloat16* __restrict__ Ahi, const __nv_bfloat16* __restrict__ Alo,
                const __nv_bfloat16* __restrict__ Bhi, const __nv_bfloat16* __restrict__ Blo,
                const float* __restrict__ bias,
                float* __restrict__ Cf,
                __nv_bfloat16* __restrict__ Chi, __nv_bfloat16* __restrict__ Clo,
                int M, int Nout) {
    constexpr int BK = 32, NT = 4;
    constexpr int NCH = KTOT / BK;
    extern __shared__ char smem[];
    __nv_bfloat16* smemb = reinterpret_cast<__nv_bfloat16*>(smem);

    int tid = threadIdx.x;
    int lane = tid & 31, wid = tid >> 5;
    int wm = wid & 3, wn = wid >> 2;
    int g = lane >> 2, t2 = (lane & 3) * 2;

    int row0 = blockIdx.y * 128;
    int col0 = blockIdx.x * 64;

    int a_r = (lane & 15);
    int a_k = (lane >> 4) * 8;
    int b_r = (lane & 7) + ((lane >> 4) & 1) * 8;
    int b_k = ((lane >> 3) & 1) * 8;

    float acc[2][NT][4];
    #pragma unroll
    for (int mt = 0; mt < 2; mt++)
        #pragma unroll
        for (int nt = 0; nt < NT; nt++)
            #pragma unroll
            for (int j = 0; j < 4; j++) acc[mt][nt][j] = 0.f;

    auto issue = [&](int c, int s) {
        int kc = c * BK;
        __nv_bfloat16* base = smemb + s * STAGE;
        #pragma unroll
        for (int u = tid; u < 512; u += 256) {
            int row = u >> 2, q = u & 3;
            int gr = row0 + row;
            bool ok = gr < M;
            const __nv_bfloat16* pH = ok ? (Ahi + (size_t)gr * KTOT + kc + q * 8) : Ahi;
            const __nv_bfloat16* pL = ok ? (Alo + (size_t)gr * KTOT + kc + q * 8) : Alo;
            cp16p((uint32_t)__cvta_generic_to_shared(base + ST_AH + row * LDSW + q * 8), pH, ok);
            cp16p((uint32_t)__cvta_generic_to_shared(base + ST_AL + row * LDSW + q * 8), pL, ok);
        }
        {
            int u = tid;
            if (u < 256) {
                int row = u >> 2, q = u & 3;
                int gn = col0 + row;
                cp16p((uint32_t)__cvta_generic_to_shared(base + ST_BH + row * LDSW + q * 8),
                      Bhi + (size_t)gn * KTOT + kc + q * 8, true);
                cp16p((uint32_t)__cvta_generic_to_shared(base + ST_BL + row * LDSW + q * 8),
                      Blo + (size_t)gn * KTOT + kc + q * 8, true);
            }
        }
        asm volatile("cp.async.commit_group;" ::: "memory");
    };

    issue(0, 0);
    if (NCH > 1) issue(1, 1);

    for (int c = 0; c < NCH; c++) {
        int s = c % NSTG;
        if (c + 2 < NCH) {
            issue(c + 2, (c + 2) % NSTG);
            asm volatile("cp.async.wait_group 2;" ::: "memory");
        } else if (c + 1 < NCH) {
            asm volatile("cp.async.wait_group 1;" ::: "memory");
        } else {
            asm volatile("cp.async.wait_group 0;" ::: "memory");
        }
        __syncthreads();

        const __nv_bfloat16* base = smemb + s * STAGE;
        const __nv_bfloat16* asH = base + ST_AH;
        const __nv_bfloat16* asL = base + ST_AL;
        const __nv_bfloat16* bsH = base + ST_BH;
        const __nv_bfloat16* bsL = base + ST_BL;

        #pragma unroll
        for (int ko = 0; ko < BK; ko += 16) {
            uint32_t ah[2][4], al[2][4];
            #pragma unroll
            for (int mt = 0; mt < 2; mt++) {
                int rb = wm * 32 + mt * 16;
                ldsm4(ah[mt], (uint32_t)__cvta_generic_to_shared(asH + (rb + a_r) * LDSW + ko + a_k));
                ldsm4(al[mt], (uint32_t)__cvta_generic_to_shared(asL + (rb + a_r) * LDSW + ko + a_k));
            }
            uint32_t bh[NT][2], bl[NT][2];
            #pragma unroll
            for (int np = 0; np < NT; np += 2) {
                int nb = wn * 32 + np * 8;
                uint32_t r4[4];
                ldsm4(r4, (uint32_t)__cvta_generic_to_shared(bsH + (nb + b_r) * LDSW + ko + b_k));
                bh[np][0] = r4[0]; bh[np][1] = r4[1];
                bh[np+1][0] = r4[2]; bh[np+1][1] = r4[3];
                ldsm4(r4, (uint32_t)__cvta_generic_to_shared(bsL + (nb + b_r) * LDSW + ko + b_k));
                bl[np][0] = r4[0]; bl[np][1] = r4[1];
                bl[np+1][0] = r4[2]; bl[np+1][1] = r4[3];
            }
            #pragma unroll
            for (int mt = 0; mt < 2; mt++)
                #pragma unroll
                for (int nt = 0; nt < NT; nt++) {
                    mma16816(acc[mt][nt], ah[mt], bh[nt]);
                    mma16816(acc[mt][nt], ah[mt], bl[nt]);
                    mma16816(acc[mt][nt], al[mt], bh[nt]);
                }
        }
        __syncthreads();
    }

    #pragma unroll
    for (int mt = 0; mt < 2; mt++) {
        int rbase = row0 + wm * 32 + mt * 16;
        #pragma unroll
        for (int half = 0; half < 2; half++) {
            int r = rbase + g + half * 8;
            if (r >= M) continue;
            #pragma unroll
            for (int nt = 0; nt < NT; nt++) {
                int c = col0 + wn * 32 + nt * 8 + t2;
                float v0 = acc[mt][nt][half * 2 + 0] + bias[c];
                float v1 = acc[mt][nt][half * 2 + 1] + bias[c + 1];
                if (EPI == 0) {
                    __nv_bfloat16 h0, l0, h1, l1;
                    split_bf16(v0, h0, l0);
                    split_bf16(v1, h1, l1);
                    __nv_bfloat162 ph; ph.x = h0; ph.y = h1;
                    __nv_bfloat162 pl; pl.x = l0; pl.y = l1;
                    *reinterpret_cast<__nv_bfloat162*>(&Chi[(size_t)r * Nout + c]) = ph;
                    *reinterpret_cast<__nv_bfloat162*>(&Clo[(size_t)r * Nout + c]) = pl;
                } else {
                    *reinterpret_cast<float2*>(&Cf[(size_t)r * Nout + c]) = make_float2(v0, v1);
                }
            }
        }
    }
}

// ---------------- launcher ----------------
extern "C" void kernel_launch(void* const* d_in, const int* in_sizes, int n_in,
                              void* d_out, int out_size) {
    const float* x      = (const float*)d_in[0];
    const int*   eidx   = (const int*)  d_in[1];
    const float* W_emb  = (const float*)d_in[2];
    const float* b_emb  = (const float*)d_in[3];
    const float* W_conv = (const float*)d_in[4];
    const float* b_conv = (const float*)d_in[5];
    const float* W_out  = (const float*)d_in[6];
    const float* b_out  = (const float*)d_in[7];
    float* out = (float*)d_out;

    int E = in_sizes[1] / 2;
    if (E > E_MAX) E = E_MAX;
    const int* src = eidx;
    const int* dst = eidx + E;
    const int n = N_NODES;

    float *dinv;
    int *cnt, *partial, *rowptr, *cursor;
    int2 *csr;
    __nv_bfloat16 *xhi, *xlo, *hhiA, *hloA, *hhiB, *hloB;
    __nv_bfloat16 *wembh, *wembl, *wconvh, *wconvl, *wouth, *woutl;
    cudaGetSymbolAddress((void**)&dinv,   g_dinv);
    cudaGetSymbolAddress((void**)&cnt,    g_cnt);
    cudaGetSymbolAddress((void**)&partial,g_partial);
    cudaGetSymbolAddress((void**)&rowptr, g_rowptr);
    cudaGetSymbolAddress((void**)&cursor, g_cursor);
    cudaGetSymbolAddress((void**)&csr,    g_csr);
    cudaGetSymbolAddress((void**)&xhi,  g_xhi);
    cudaGetSymbolAddress((void**)&xlo,  g_xlo);
    cudaGetSymbolAddress((void**)&hhiA, g_hhiA);
    cudaGetSymbolAddress((void**)&hloA, g_hloA);
    cudaGetSymbolAddress((void**)&hhiB, g_hhiB);
    cudaGetSymbolAddress((void**)&hloB, g_hloB);
    cudaGetSymbolAddress((void**)&wembh, g_wembh);
    cudaGetSymbolAddress((void**)&wembl, g_wembl);
    cudaGetSymbolAddress((void**)&wconvh, g_wconvh);
    cudaGetSymbolAddress((void**)&wconvl, g_wconvl);
    cudaGetSymbolAddress((void**)&wouth, g_wouth);
    cudaGetSymbolAddress((void**)&woutl, g_woutl);

    const int SMEM_GEMM = NSTG * STAGE * (int)sizeof(__nv_bfloat16);
    cudaFuncSetAttribute(k_mma_gemm<DIN, 0>, cudaFuncAttributeMaxDynamicSharedMemorySize, SMEM_GEMM);
    cudaFuncSetAttribute(k_mma_gemm<DH, 2>,  cudaFuncAttributeMaxDynamicSharedMemorySize, SMEM_GEMM);
    cudaFuncSetAttribute(k_layer, cudaFuncAttributeMaxDynamicSharedMemorySize, L_SMEM);

    // CSR build + dinv
    k_zero <<<(n + 255) / 256, 256>>>(cnt, n);
    k_count<<<(E + 255) / 256, 256>>>(dst, cnt, E);
    k_dinv <<<(n + 255) / 256, 256>>>(cnt, dinv, n);
    k_scan1<<<SCAN_NB, 256>>>(cnt, partial, n);
    k_scan2<<<1, 64>>>(partial, rowptr, SCAN_NB, n);
    k_scan3<<<SCAN_NB, 256>>>(cnt, partial, rowptr, cursor, n);
    k_fill <<<(E + 255) / 256, 256>>>(src, dst, dinv, cursor, csr, E);

    // conversions
    k_conv_x<<<(n * DIN + 255) / 256, 256>>>(x, xhi, xlo, n * DIN);
    k_conv_w<<<(DIN * DH + 255) / 256, 256>>>(W_emb, wembh, wembl, DIN, DH);
    for (int l = 0; l < LAYERS; l++)
        k_conv_w<<<(DH * DH + 255) / 256, 256>>>(W_conv + (size_t)l * DH * DH,
                                                 wconvh + (size_t)l * DH * DH,
                                                 wconvl + (size_t)l * DH * DH, DH, DH);
    k_conv_w<<<(DH * DOUT + 255) / 256, 256>>>(W_out, wouth, woutl, DH, DOUT);

    int gy = (n + 127) / 128;

    // embedding: h0 = x @ W_emb + b_emb -> bf16 split (buffer A)
    {
        dim3 grid(DH / 64, gy);
        k_mma_gemm<DIN, 0><<<grid, 256, SMEM_GEMM>>>(xhi, xlo, wembh, wembl, b_emb,
                                                     nullptr, hhiA, hloA, n, DH);
    }

    // fused conv layers (ping-pong A <-> B)
    int lgrid = (n + 63) / 64;    // 782
    __nv_bfloat16* bufs[2][2] = { { hhiA, hloA }, { hhiB, hloB } };
    for (int l = 0; l < LAYERS; l++) {
        __nv_bfloat16* iH = bufs[l & 1][0];
        __nv_bfloat16* iL = bufs[l & 1][1];
        __nv_bfloat16* oH = bufs[(l + 1) & 1][0];
        __nv_bfloat16* oL = bufs[(l + 1) & 1][1];
        k_layer<<<lgrid, 256, L_SMEM>>>(iH, iL, csr, rowptr, dinv,
                                        wconvh + (size_t)l * DH * DH,
                                        wconvl + (size_t)l * DH * DH,
                                        b_conv + (size_t)l * DH,
                                        oH, oL, n);
    }

    // output: out = h4 @ W_out + b_out  (h4 in buffer A since LAYERS is even)
    {
        dim3 grid(DOUT / 64, gy);
        k_mma_gemm<DH, 2><<<grid, 256, SMEM_GEMM>>>(hhiA, hloA, wouth, woutl, b_out,
                                                    out, nullptr, nullptr, n, DOUT);
    }
}

// round 14
// speedup vs baseline: 1.4430x; 1.4430x over previous
#include <cuda_runtime.h>
#include <cuda_bf16.h>
#include <cstdint>
#include <math.h>

#define N_NODES 50000
#define E_MAX   800000
#define DIN     128
#define DH      256
#define DOUT    64
#define LAYERS  4

#define SCAN_NB  ((N_NODES + 1023) / 1024)   // 49

// ---------------- device scratch (allocation-free) ----------------
__device__ float g_dinv[N_NODES];
__device__ int   g_cnt[N_NODES];
__device__ int   g_partial[64];
__device__ int   g_rowptr[N_NODES + 1];
__device__ int   g_cursor[N_NODES];
__device__ int2  g_csr[E_MAX];                    // {src, norm-as-int}
__device__ float g_ht [(size_t)N_NODES * DH];
__device__ __nv_bfloat16 g_xhi[(size_t)N_NODES * DIN];
__device__ __nv_bfloat16 g_xlo[(size_t)N_NODES * DIN];
__device__ __nv_bfloat16 g_hhi[(size_t)N_NODES * DH];
__device__ __nv_bfloat16 g_hlo[(size_t)N_NODES * DH];
// transposed bf16 weights [N][K] (K-major rows)
__device__ __nv_bfloat16 g_wembh[DH * DIN], g_wembl[DH * DIN];
__device__ __nv_bfloat16 g_wconvh[LAYERS * DH * DH], g_wconvl[LAYERS * DH * DH];
__device__ __nv_bfloat16 g_wouth[DOUT * DH], g_woutl[DOUT * DH];

// ---------------- CSR build ----------------
__global__ void k_zero(int* cnt, int n) {
    int i = blockIdx.x * blockDim.x + threadIdx.x;
    if (i < n) cnt[i] = 0;
}
__global__ void k_count(const int* __restrict__ dst, int* cnt, int E) {
    int e = blockIdx.x * blockDim.x + threadIdx.x;
    if (e < E) atomicAdd(&cnt[dst[e]], 1);
}
__global__ void k_dinv(const int* __restrict__ cnt, float* dinv, int n) {
    int i = blockIdx.x * blockDim.x + threadIdx.x;
    if (i < n) dinv[i] = rsqrtf((float)cnt[i] + 1.0f);   // +1 self-loop
}
__global__ void k_scan1(const int* __restrict__ cnt, int* partial, int n) {
    __shared__ int sd[256];
    int base = blockIdx.x * 1024;
    int t = threadIdx.x;
    int s = 0;
    #pragma unroll
    for (int i = 0; i < 4; i++) {
        int idx = base + t + i * 256;
        if (idx < n) s += cnt[idx];
    }
    sd[t] = s;
    __syncthreads();
    #pragma unroll
    for (int off = 128; off > 0; off >>= 1) {
        if (t < off) sd[t] += sd[t + off];
        __syncthreads();
    }
    if (t == 0) partial[blockIdx.x] = sd[0];
}
__global__ void k_scan2(int* partial, int* rowptr, int nb, int n) {
    __shared__ int sh[64];
    int t = threadIdx.x;
    int v = (t < nb) ? partial[t] : 0;
    sh[t] = v;
    __syncthreads();
    #pragma unroll
    for (int off = 1; off < 64; off <<= 1) {
        int x = (t >= off) ? sh[t - off] : 0;
        __syncthreads();
        sh[t] += x;
        __syncthreads();
    }
    if (t < nb) partial[t] = sh[t] - v;      // exclusive
    if (t == 63) rowptr[n] = sh[63];
}
__global__ void k_scan3(const int* __restrict__ cnt, const int* __restrict__ partial,
                        int* rowptr, int* cursor, int n) {
    __shared__ int sh[256];
    int base = blockIdx.x * 1024;
    int t = threadIdx.x;
    int i0 = base + t * 4;
    int c0 = (i0     < n) ? cnt[i0    ] : 0;
    int c1 = (i0 + 1 < n) ? cnt[i0 + 1] : 0;
    int c2 = (i0 + 2 < n) ? cnt[i0 + 2] : 0;
    int c3 = (i0 + 3 < n) ? cnt[i0 + 3] : 0;
    int tot = c0 + c1 + c2 + c3;
    sh[t] = tot;
    __syncthreads();
    #pragma unroll
    for (int off = 1; off < 256; off <<= 1) {
        int x = (t >= off) ? sh[t - off] : 0;
        __syncthreads();
        sh[t] += x;
        __syncthreads();
    }
    int run = sh[t] - tot + partial[blockIdx.x];
    if (i0     < n) { rowptr[i0    ] = run; cursor[i0    ] = run; run += c0; }
    if (i0 + 1 < n) { rowptr[i0 + 1] = run; cursor[i0 + 1] = run; run += c1; }
    if (i0 + 2 < n) { rowptr[i0 + 2] = run; cursor[i0 + 2] = run; run += c2; }
    if (i0 + 3 < n) { rowptr[i0 + 3] = run; cursor[i0 + 3] = run; }
}
__global__ void k_fill(const int* __restrict__ src, const int* __restrict__ dst,
                       const float* __restrict__ dinv, int* cursor,
                       int2* __restrict__ csr, int E) {
    int e = blockIdx.x * blockDim.x + threadIdx.x;
    if (e >= E) return;
    int s = src[e], d = dst[e];
    int pos = atomicAdd(&cursor[d], 1);
    float w = dinv[s] * dinv[d];
    csr[pos] = make_int2(s, __float_as_int(w));
}

// ---------------- conversions ----------------
__device__ __forceinline__ void split_bf16(float v, __nv_bfloat16& hi, __nv_bfloat16& lo) {
    hi = __float2bfloat16_rn(v);
    lo = __float2bfloat16_rn(v - __bfloat162float(hi));
}
__global__ void k_conv_x(const float* __restrict__ x,
                         __nv_bfloat16* __restrict__ hi, __nv_bfloat16* __restrict__ lo,
                         int total) {
    int i = blockIdx.x * blockDim.x + threadIdx.x;
    if (i >= total) return;
    split_bf16(x[i], hi[i], lo[i]);
}
__global__ void k_conv_w(const float* __restrict__ W,
                         __nv_bfloat16* __restrict__ hi, __nv_bfloat16* __restrict__ lo,
                         int K, int N) {
    int i = blockIdx.x * blockDim.x + threadIdx.x;
    if (i >= K * N) return;
    int k = i / N, n = i % N;
    __nv_bfloat16 h, l;
    split_bf16(W[i], h, l);
    hi[(size_t)n * K + k] = h;
    lo[(size_t)n * K + k] = l;
}

// ---------------- mma.sync bf16 GEMM, 3-term compensated, cp.async 2-stage ----------------
__device__ __forceinline__ void mma16816(float* c, const uint32_t* a, const uint32_t* b) {
    asm volatile(
        "mma.sync.aligned.m16n8k16.row.col.f32.bf16.bf16.f32 "
        "{%0,%1,%2,%3}, {%4,%5,%6,%7}, {%8,%9}, {%0,%1,%2,%3};"
        : "+f"(c[0]), "+f"(c[1]), "+f"(c[2]), "+f"(c[3])
        : "r"(a[0]), "r"(a[1]), "r"(a[2]), "r"(a[3]), "r"(b[0]), "r"(b[1]));
}
__device__ __forceinline__ void cp16p(uint32_t dst, const void* src, bool valid) {
    int sz = valid ? 16 : 0;
    asm volatile("cp.async.cg.shared.global [%0], [%1], 16, %2;"
                 :: "r"(dst), "l"(src), "r"(sz) : "memory");
}

// smem layout per stage (elements): AsH[128*40] AsL[128*40] BsH[64*40] BsL[64*40]
#define LDSW  40
#define ST_AH 0
#define ST_AL (128 * LDSW)
#define ST_BH (2 * 128 * LDSW)
#define ST_BL (2 * 128 * LDSW + 64 * LDSW)
#define STAGE (2 * 128 * LDSW + 2 * 64 * LDSW)   // 15360 elements

template<int KTOT, int EPI>
__global__ __launch_bounds__(256, 2)
void k_mma_gemm(const __nv_bfloat16* __restrict__ Ahi, const __nv_bfloat16* __restrict__ Alo,
                const __nv_bfloat16* __restrict__ Bhi, const __nv_bfloat16* __restrict__ Blo,
                const float* __restrict__ bias,
                float* __restrict__ Cf,
                __nv_bfloat16* __restrict__ Chi, __nv_bfloat16* __restrict__ Clo,
                int M, int Nout) {
    constexpr int BK = 32, NT = 4;
    constexpr int NCH = KTOT / BK;
    extern __shared__ char smem_raw[];
    __nv_bfloat16* smem = reinterpret_cast<__nv_bfloat16*>(smem_raw);

    int tid = threadIdx.x;
    int lane = tid & 31, wid = tid >> 5;
    int wm = wid & 3, wn = wid >> 2;
    int g = lane >> 2, t2 = (lane & 3) * 2;

    int row0 = blockIdx.y * 128;
    int col0 = blockIdx.x * 64;

    float acc[2][NT][4];
    #pragma unroll
    for (int mt = 0; mt < 2; mt++)
        #pragma unroll
        for (int nt = 0; nt < NT; nt++)
            #pragma unroll
            for (int j = 0; j < 4; j++) acc[mt][nt][j] = 0.f;

    // async load of chunk kc into stage s
    auto issue = [&](int c, int s) {
        int kc = c * BK;
        __nv_bfloat16* base = smem + s * STAGE;
        #pragma unroll
        for (int u = tid; u < 512; u += 256) {
            int row = u >> 2, q = u & 3;
            int gr = row0 + row;
            bool ok = gr < M;
            const __nv_bfloat16* pH = ok ? (Ahi + (size_t)gr * KTOT + kc + q * 8) : Ahi;
            const __nv_bfloat16* pL = ok ? (Alo + (size_t)gr * KTOT + kc + q * 8) : Alo;
            cp16p((uint32_t)__cvta_generic_to_shared(base + ST_AH + row * LDSW + q * 8), pH, ok);
            cp16p((uint32_t)__cvta_generic_to_shared(base + ST_AL + row * LDSW + q * 8), pL, ok);
        }
        {
            int u = tid;
            if (u < 256) {
                int row = u >> 2, q = u & 3;
                int gn = col0 + row;
                cp16p((uint32_t)__cvta_generic_to_shared(base + ST_BH + row * LDSW + q * 8),
                      Bhi + (size_t)gn * KTOT + kc + q * 8, true);
                cp16p((uint32_t)__cvta_generic_to_shared(base + ST_BL + row * LDSW + q * 8),
                      Blo + (size_t)gn * KTOT + kc + q * 8, true);
            }
        }
        asm volatile("cp.async.commit_group;" ::: "memory");
    };

    issue(0, 0);

    for (int c = 0; c < NCH; c++) {
        int s = c & 1;
        if (c + 1 < NCH) {
            issue(c + 1, (c + 1) & 1);
            asm volatile("cp.async.wait_group 1;" ::: "memory");
        } else {
            asm volatile("cp.async.wait_group 0;" ::: "memory");
        }
        __syncthreads();

        const __nv_bfloat16* base = smem + s * STAGE;
        const __nv_bfloat16* asH = base + ST_AH;
        const __nv_bfloat16* asL = base + ST_AL;
        const __nv_bfloat16* bsH = base + ST_BH;
        const __nv_bfloat16* bsL = base + ST_BL;

        #pragma unroll
        for (int ko = 0; ko < BK; ko += 16) {
            uint32_t ah[2][4], al[2][4];
            #pragma unroll
            for (int mt = 0; mt < 2; mt++) {
                int rb = wm * 32 + mt * 16;
                ah[mt][0] = *reinterpret_cast<const uint32_t*>(asH + (rb + g    ) * LDSW + ko + t2    );
                ah[mt][1] = *reinterpret_cast<const uint32_t*>(asH + (rb + g + 8) * LDSW + ko + t2    );
                ah[mt][2] = *reinterpret_cast<const uint32_t*>(asH + (rb + g    ) * LDSW + ko + t2 + 8);
                ah[mt][3] = *reinterpret_cast<const uint32_t*>(asH + (rb + g + 8) * LDSW + ko + t2 + 8);
                al[mt][0] = *reinterpret_cast<const uint32_t*>(asL + (rb + g    ) * LDSW + ko + t2    );
                al[mt][1] = *reinterpret_cast<const uint32_t*>(asL + (rb + g + 8) * LDSW + ko + t2    );
                al[mt][2] = *reinterpret_cast<const uint32_t*>(asL + (rb + g    ) * LDSW + ko + t2 + 8);
                al[mt][3] = *reinterpret_cast<const uint32_t*>(asL + (rb + g + 8) * LDSW + ko + t2 + 8);
            }
            uint32_t bh[NT][2], bl[NT][2];
            #pragma unroll
            for (int nt = 0; nt < NT; nt++) {
                int nb = wn * 32 + nt * 8 + g;
                bh[nt][0] = *reinterpret_cast<const uint32_t*>(bsH + nb * LDSW + ko + t2    );
                bh[nt][1] = *reinterpret_cast<const uint32_t*>(bsH + nb * LDSW + ko + t2 + 8);
                bl[nt][0] = *reinterpret_cast<const uint32_t*>(bsL + nb * LDSW + ko + t2    );
                bl[nt][1] = *reinterpret_cast<const uint32_t*>(bsL + nb * LDSW + ko + t2 + 8);
            }
            #pragma unroll
            for (int mt = 0; mt < 2; mt++)
                #pragma unroll
                for (int nt = 0; nt < NT; nt++) {
                    mma16816(acc[mt][nt], ah[mt], bh[nt]);
                    mma16816(acc[mt][nt], ah[mt], bl[nt]);
                    mma16816(acc[mt][nt], al[mt], bh[nt]);
                }
        }
        __syncthreads();
    }

    #pragma unroll
    for (int mt = 0; mt < 2; mt++) {
        int rbase = row0 + wm * 32 + mt * 16;
        #pragma unroll
        for (int half = 0; half < 2; half++) {
            int r = rbase + g + half * 8;
            if (r >= M) continue;
            #pragma unroll
            for (int nt = 0; nt < NT; nt++) {
                int c = col0 + wn * 32 + nt * 8 + t2;
                float v0 = acc[mt][nt][half * 2 + 0];
                float v1 = acc[mt][nt][half * 2 + 1];
                if (EPI != 1) { v0 += bias[c]; v1 += bias[c + 1]; }
                if (EPI == 0) {
                    __nv_bfloat16 h0, l0, h1, l1;
                    split_bf16(v0, h0, l0);
                    split_bf16(v1, h1, l1);
                    __nv_bfloat162 ph; ph.x = h0; ph.y = h1;
                    __nv_bfloat162 pl; pl.x = l0; pl.y = l1;
                    *reinterpret_cast<__nv_bfloat162*>(&Chi[(size_t)r * Nout + c]) = ph;
                    *reinterpret_cast<__nv_bfloat162*>(&Clo[(size_t)r * Nout + c]) = pl;
                } else {
                    *reinterpret_cast<float2*>(&Cf[(size_t)r * Nout + c]) = make_float2(v0, v1);
                }
            }
        }
    }
}

// ---------------- fused gather aggregation ----------------
__global__ __launch_bounds__(256)
void k_gather(const float* __restrict__ ht, const int2* __restrict__ csr,
              const int* __restrict__ rowptr, const float* __restrict__ dinv,
              const float* __restrict__ b,
              __nv_bfloat16* __restrict__ hhi, __nv_bfloat16* __restrict__ hlo, int n) {
    int warp = (blockIdx.x * blockDim.x + threadIdx.x) >> 5;
    int lane = threadIdx.x & 31;
    if (warp >= n) return;
    int i = warp;

    float di = dinv[i];
    float w0 = di * di;
    const float4* row = reinterpret_cast<const float4*>(ht + (size_t)i * DH);
    float4 a0 = row[lane * 2], a1 = row[lane * 2 + 1];
    float acc[8] = { a0.x * w0, a0.y * w0, a0.z * w0, a0.w * w0,
                     a1.x * w0, a1.y * w0, a1.z * w0, a1.w * w0 };

    int beg = rowptr[i], end = rowptr[i + 1];
    int j = beg;
    for (; j + 1 < end; j += 2) {
        int2 e0 = csr[j], e1 = csr[j + 1];
        const float4* r0 = reinterpret_cast<const float4*>(ht + (size_t)e0.x * DH);
        const float4* r1 = reinterpret_cast<const float4*>(ht + (size_t)e1.x * DH);
        float wa = __int_as_float(e0.y), wb = __int_as_float(e1.y);
        float4 v0 = r0[lane * 2], v1 = r0[lane * 2 + 1];
        float4 u0 = r1[lane * 2], u1 = r1[lane * 2 + 1];
        acc[0] += v0.x * wa; acc[1] += v0.y * wa; acc[2] += v0.z * wa; acc[3] += v0.w * wa;
        acc[4] += v1.x * wa; acc[5] += v1.y * wa; acc[6] += v1.z * wa; acc[7] += v1.w * wa;
        acc[0] += u0.x * wb; acc[1] += u0.y * wb; acc[2] += u0.z * wb; acc[3] += u0.w * wb;
        acc[4] += u1.x * wb; acc[5] += u1.y * wb; acc[6] += u1.z * wb; acc[7] += u1.w * wb;
    }
    if (j < end) {
        int2 e0 = csr[j];
        const float4* r0 = reinterpret_cast<const float4*>(ht + (size_t)e0.x * DH);
        float wa = __int_as_float(e0.y);
        float4 v0 = r0[lane * 2], v1 = r0[lane * 2 + 1];
        acc[0] += v0.x * wa; acc[1] += v0.y * wa; acc[2] += v0.z * wa; acc[3] += v0.w * wa;
        acc[4] += v1.x * wa; acc[5] += v1.y * wa; acc[6] += v1.z * wa; acc[7] += v1.w * wa;
    }

    const float4* bp = reinterpret_cast<const float4*>(b);
    float4 b0 = bp[lane * 2], b1 = bp[lane * 2 + 1];
    float bb[8] = { b0.x, b0.y, b0.z, b0.w, b1.x, b1.y, b1.z, b1.w };

    __nv_bfloat16 hh[8], ll[8];
    #pragma unroll
    for (int q = 0; q < 8; q++) {
        float v = tanhf(acc[q] + bb[q]);
        split_bf16(v, hh[q], ll[q]);
    }
    *reinterpret_cast<uint4*>(hhi + (size_t)i * DH + lane * 8) = *reinterpret_cast<uint4*>(hh);
    *reinterpret_cast<uint4*>(hlo + (size_t)i * DH + lane * 8) = *reinterpret_cast<uint4*>(ll);
}

// ---------------- launcher ----------------
extern "C" void kernel_launch(void* const* d_in, const int* in_sizes, int n_in,
                              void* d_out, int out_size) {
    const float* x      = (const float*)d_in[0];
    const int*   eidx   = (const int*)  d_in[1];
    const float* W_emb  = (const float*)d_in[2];
    const float* b_emb  = (const float*)d_in[3];
    const float* W_conv = (const float*)d_in[4];
    const float* b_conv = (const float*)d_in[5];
    const float* W_out  = (const float*)d_in[6];
    const float* b_out  = (const float*)d_in[7];
    float* out = (float*)d_out;

    int E = in_sizes[1] / 2;
    if (E > E_MAX) E = E_MAX;
    const int* src = eidx;
    const int* dst = eidx + E;
    const int n = N_NODES;

    float *dinv, *ht;
    int *cnt, *partial, *rowptr, *cursor;
    int2 *csr;
    __nv_bfloat16 *xhi, *xlo, *hhi, *hlo;
    __nv_bfloat16 *wembh, *wembl, *wconvh, *wconvl, *wouth, *woutl;
    cudaGetSymbolAddress((void**)&dinv,   g_dinv);
    cudaGetSymbolAddress((void**)&cnt,    g_cnt);
    cudaGetSymbolAddress((void**)&partial,g_partial);
    cudaGetSymbolAddress((void**)&rowptr, g_rowptr);
    cudaGetSymbolAddress((void**)&cursor, g_cursor);
    cudaGetSymbolAddress((void**)&csr,    g_csr);
    cudaGetSymbolAddress((void**)&ht,   g_ht);
    cudaGetSymbolAddress((void**)&xhi,  g_xhi);
    cudaGetSymbolAddress((void**)&xlo,  g_xlo);
    cudaGetSymbolAddress((void**)&hhi,  g_hhi);
    cudaGetSymbolAddress((void**)&hlo,  g_hlo);
    cudaGetSymbolAddress((void**)&wembh, g_wembh);
    cudaGetSymbolAddress((void**)&wembl, g_wembl);
    cudaGetSymbolAddress((void**)&wconvh, g_wconvh);
    cudaGetSymbolAddress((void**)&wconvl, g_wconvl);
    cudaGetSymbolAddress((void**)&wouth, g_wouth);
    cudaGetSymbolAddress((void**)&woutl, g_woutl);

    const int SMEM_GEMM = 2 * STAGE * (int)sizeof(__nv_bfloat16);   // 61440
    cudaFuncSetAttribute(k_mma_gemm<DIN, 0>, cudaFuncAttributeMaxDynamicSharedMemorySize, SMEM_GEMM);
    cudaFuncSetAttribute(k_mma_gemm<DH, 1>,  cudaFuncAttributeMaxDynamicSharedMemorySize, SMEM_GEMM);
    cudaFuncSetAttribute(k_mma_gemm<DH, 2>,  cudaFuncAttributeMaxDynamicSharedMemorySize, SMEM_GEMM);

    // CSR build + dinv
    k_zero <<<(n + 255) / 256, 256>>>(cnt, n);
    k_count<<<(E + 255) / 256, 256>>>(dst, cnt, E);
    k_dinv <<<(n + 255) / 256, 256>>>(cnt, dinv, n);
    k_scan1<<<SCAN_NB, 256>>>(cnt, partial, n);
    k_scan2<<<1, 64>>>(partial, rowptr, SCAN_NB, n);
    k_scan3<<<SCAN_NB, 256>>>(cnt, partial, rowptr, cursor, n);
    k_fill <<<(E + 255) / 256, 256>>>(src, dst, dinv, cursor, csr, E);

    // conversions
    k_conv_x<<<(n * DIN + 255) / 256, 256>>>(x, xhi, xlo, n * DIN);
    k_conv_w<<<(DIN * DH + 255) / 256, 256>>>(W_emb, wembh, wembl, DIN, DH);
    for (int l = 0; l < LAYERS; l++)
        k_conv_w<<<(DH * DH + 255) / 256, 256>>>(W_conv + (size_t)l * DH * DH,
                                                 wconvh + (size_t)l * DH * DH,
                                                 wconvl + (size_t)l * DH * DH, DH, DH);
    k_conv_w<<<(DH * DOUT + 255) / 256, 256>>>(W_out, wouth, woutl, DH, DOUT);

    int gy = (n + 127) / 128;

    // embedding: h = x @ W_emb + b_emb -> bf16 split
    {
        dim3 grid(DH / 64, gy);
        k_mma_gemm<DIN, 0><<<grid, 256, SMEM_GEMM>>>(xhi, xlo, wembh, wembl, b_emb,
                                                     nullptr, hhi, hlo, n, DH);
    }

    int gather_blocks = (n * 32 + 255) / 256;
    for (int l = 0; l < LAYERS; l++) {
        const float* b = b_conv + (size_t)l * DH;
        dim3 grid(DH / 64, gy);
        k_mma_gemm<DH, 1><<<grid, 256, SMEM_GEMM>>>(hhi, hlo,
                                                    wconvh + (size_t)l * DH * DH,
                                                    wconvl + (size_t)l * DH * DH,
                                                    nullptr, ht, nullptr, nullptr, n, DH);
        k_gather<<<gather_blocks, 256>>>(ht, csr, rowptr, dinv, b, hhi, hlo, n);
    }

    // output: out = h @ W_out + b_out
    {
        dim3 grid(DOUT / 64, gy);
        k_mma_gemm<DH, 2><<<grid, 256, SMEM_GEMM>>>(hhi, hlo, wouth, woutl, b_out,
                                                    out, nullptr, nullptr, n, DOUT);
    }
}

// round 15
// speedup vs baseline: 1.7068x; 1.1828x over previous
#include <cuda_runtime.h>
#include <cuda_bf16.h>
#include <cuda_fp16.h>
#include <cstdint>
#include <math.h>

#define N_NODES 50000
#define E_MAX   800000
#define DIN     128
#define DH      256
#define DOUT    64
#define LAYERS  4

#define SCAN_NB  ((N_NODES + 1023) / 1024)   // 49

// ---------------- device scratch (allocation-free) ----------------
__device__ float g_dinv[N_NODES];
__device__ int   g_cnt[N_NODES];
__device__ int   g_partial[64];
__device__ int   g_rowptr[N_NODES + 1];
__device__ int   g_cursor[N_NODES];
__device__ int2  g_csr[E_MAX];                    // {src, norm-as-int}
__device__ __half g_ht[(size_t)N_NODES * DH];     // fp16 pre-activation (gather path)
__device__ __nv_bfloat16 g_xhi[(size_t)N_NODES * DIN];
__device__ __nv_bfloat16 g_xlo[(size_t)N_NODES * DIN];
__device__ __nv_bfloat16 g_hhi[(size_t)N_NODES * DH];
__device__ __nv_bfloat16 g_hlo[(size_t)N_NODES * DH];
// transposed bf16 weights [N][K] (K-major rows)
__device__ __nv_bfloat16 g_wembh[DH * DIN], g_wembl[DH * DIN];
__device__ __nv_bfloat16 g_wconvh[LAYERS * DH * DH], g_wconvl[LAYERS * DH * DH];
__device__ __nv_bfloat16 g_wouth[DOUT * DH], g_woutl[DOUT * DH];

// ---------------- CSR build ----------------
__global__ void k_zero(int* cnt, int n) {
    int i = blockIdx.x * blockDim.x + threadIdx.x;
    if (i < n) cnt[i] = 0;
}
__global__ void k_count(const int* __restrict__ dst, int* cnt, int E) {
    int e = blockIdx.x * blockDim.x + threadIdx.x;
    if (e < E) atomicAdd(&cnt[dst[e]], 1);
}
__global__ void k_dinv(const int* __restrict__ cnt, float* dinv, int n) {
    int i = blockIdx.x * blockDim.x + threadIdx.x;
    if (i < n) dinv[i] = rsqrtf((float)cnt[i] + 1.0f);   // +1 self-loop
}
__global__ void k_scan1(const int* __restrict__ cnt, int* partial, int n) {
    __shared__ int sd[256];
    int base = blockIdx.x * 1024;
    int t = threadIdx.x;
    int s = 0;
    #pragma unroll
    for (int i = 0; i < 4; i++) {
        int idx = base + t + i * 256;
        if (idx < n) s += cnt[idx];
    }
    sd[t] = s;
    __syncthreads();
    #pragma unroll
    for (int off = 128; off > 0; off >>= 1) {
        if (t < off) sd[t] += sd[t + off];
        __syncthreads();
    }
    if (t == 0) partial[blockIdx.x] = sd[0];
}
__global__ void k_scan2(int* partial, int* rowptr, int nb, int n) {
    __shared__ int sh[64];
    int t = threadIdx.x;
    int v = (t < nb) ? partial[t] : 0;
    sh[t] = v;
    __syncthreads();
    #pragma unroll
    for (int off = 1; off < 64; off <<= 1) {
        int x = (t >= off) ? sh[t - off] : 0;
        __syncthreads();
        sh[t] += x;
        __syncthreads();
    }
    if (t < nb) partial[t] = sh[t] - v;      // exclusive
    if (t == 63) rowptr[n] = sh[63];
}
__global__ void k_scan3(const int* __restrict__ cnt, const int* __restrict__ partial,
                        int* rowptr, int* cursor, int n) {
    __shared__ int sh[256];
    int base = blockIdx.x * 1024;
    int t = threadIdx.x;
    int i0 = base + t * 4;
    int c0 = (i0     < n) ? cnt[i0    ] : 0;
    int c1 = (i0 + 1 < n) ? cnt[i0 + 1] : 0;
    int c2 = (i0 + 2 < n) ? cnt[i0 + 2] : 0;
    int c3 = (i0 + 3 < n) ? cnt[i0 + 3] : 0;
    int tot = c0 + c1 + c2 + c3;
    sh[t] = tot;
    __syncthreads();
    #pragma unroll
    for (int off = 1; off < 256; off <<= 1) {
        int x = (t >= off) ? sh[t - off] : 0;
        __syncthreads();
        sh[t] += x;
        __syncthreads();
    }
    int run = sh[t] - tot + partial[blockIdx.x];
    if (i0     < n) { rowptr[i0    ] = run; cursor[i0    ] = run; run += c0; }
    if (i0 + 1 < n) { rowptr[i0 + 1] = run; cursor[i0 + 1] = run; run += c1; }
    if (i0 + 2 < n) { rowptr[i0 + 2] = run; cursor[i0 + 2] = run; run += c2; }
    if (i0 + 3 < n) { rowptr[i0 + 3] = run; cursor[i0 + 3] = run; }
}
__global__ void k_fill(const int* __restrict__ src, const int* __restrict__ dst,
                       const float* __restrict__ dinv, int* cursor,
                       int2* __restrict__ csr, int E) {
    int e = blockIdx.x * blockDim.x + threadIdx.x;
    if (e >= E) return;
    int s = src[e], d = dst[e];
    int pos = atomicAdd(&cursor[d], 1);
    float w = dinv[s] * dinv[d];
    csr[pos] = make_int2(s, __float_as_int(w));
}

// ---------------- conversions ----------------
__device__ __forceinline__ void split_bf16(float v, __nv_bfloat16& hi, __nv_bfloat16& lo) {
    hi = __float2bfloat16_rn(v);
    lo = __float2bfloat16_rn(v - __bfloat162float(hi));
}
__global__ void k_conv_x(const float* __restrict__ x,
                         __nv_bfloat16* __restrict__ hi, __nv_bfloat16* __restrict__ lo,
                         int total) {
    int i = blockIdx.x * blockDim.x + threadIdx.x;
    if (i >= total) return;
    split_bf16(x[i], hi[i], lo[i]);
}
// W [K][N] fp32 -> out [N][K] bf16 hi/lo
__global__ void k_conv_w(const float* __restrict__ W,
                         __nv_bfloat16* __restrict__ hi, __nv_bfloat16* __restrict__ lo,
                         int K, int N) {
    int i = blockIdx.x * blockDim.x + threadIdx.x;
    if (i >= K * N) return;
    int k = i / N, n = i % N;
    __nv_bfloat16 h, l;
    split_bf16(W[i], h, l);
    hi[(size_t)n * K + k] = h;
    lo[(size_t)n * K + k] = l;
}
// all conv layers in one launch
__global__ void k_conv_wall(const float* __restrict__ W,
                            __nv_bfloat16* __restrict__ hi, __nv_bfloat16* __restrict__ lo) {
    int i = blockIdx.x * blockDim.x + threadIdx.x;
    if (i >= LAYERS * DH * DH) return;
    int l = i / (DH * DH);
    int r = i % (DH * DH);
    int k = r / DH, n = r % DH;
    __nv_bfloat16 h, lw;
    split_bf16(W[i], h, lw);
    size_t o = (size_t)l * DH * DH + (size_t)n * DH + k;
    hi[o] = h;
    lo[o] = lw;
}

// ---------------- mma.sync bf16 GEMM, 3-term compensated, cp.async 2-stage ----------------
__device__ __forceinline__ void mma16816(float* c, const uint32_t* a, const uint32_t* b) {
    asm volatile(
        "mma.sync.aligned.m16n8k16.row.col.f32.bf16.bf16.f32 "
        "{%0,%1,%2,%3}, {%4,%5,%6,%7}, {%8,%9}, {%0,%1,%2,%3};"
        : "+f"(c[0]), "+f"(c[1]), "+f"(c[2]), "+f"(c[3])
        : "r"(a[0]), "r"(a[1]), "r"(a[2]), "r"(a[3]), "r"(b[0]), "r"(b[1]));
}
__device__ __forceinline__ void cp16p(uint32_t dst, const void* src, bool valid) {
    int sz = valid ? 16 : 0;
    asm volatile("cp.async.cg.shared.global [%0], [%1], 16, %2;"
                 :: "r"(dst), "l"(src), "r"(sz) : "memory");
}

// smem layout per stage (elements): AsH[128*40] AsL[128*40] BsH[64*40] BsL[64*40]
#define LDSW  40
#define ST_AH 0
#define ST_AL (128 * LDSW)
#define ST_BH (2 * 128 * LDSW)
#define ST_BL (2 * 128 * LDSW + 64 * LDSW)
#define STAGE (2 * 128 * LDSW + 2 * 64 * LDSW)   // 15360 elements

// EPI: 0 = bias + bf16 split out (emb), 1 = fp16 ht write (conv), 2 = bias + fp32 (out)
template<int KTOT, int EPI>
__global__ __launch_bounds__(256)
void k_mma_gemm(const __nv_bfloat16* __restrict__ Ahi, const __nv_bfloat16* __restrict__ Alo,
                const __nv_bfloat16* __restrict__ Bhi, const __nv_bfloat16* __restrict__ Blo,
                const float* __restrict__ bias,
                float* __restrict__ Cf, __half* __restrict__ Chf,
                __nv_bfloat16* __restrict__ Chi, __nv_bfloat16* __restrict__ Clo,
                int M, int Nout) {
    constexpr int BK = 32, NT = 4;
    constexpr int NCH = KTOT / BK;
    extern __shared__ char smem_raw[];
    __nv_bfloat16* smem = reinterpret_cast<__nv_bfloat16*>(smem_raw);

    int tid = threadIdx.x;
    int lane = tid & 31, wid = tid >> 5;
    int wm = wid & 3, wn = wid >> 2;
    int g = lane >> 2, t2 = (lane & 3) * 2;

    int row0 = blockIdx.y * 128;
    int col0 = blockIdx.x * 64;

    float acc[2][NT][4];
    #pragma unroll
    for (int mt = 0; mt < 2; mt++)
        #pragma unroll
        for (int nt = 0; nt < NT; nt++)
            #pragma unroll
            for (int j = 0; j < 4; j++) acc[mt][nt][j] = 0.f;

    auto issue = [&](int c, int s) {
        int kc = c * BK;
        __nv_bfloat16* base = smem + s * STAGE;
        #pragma unroll
        for (int u = tid; u < 512; u += 256) {
            int row = u >> 2, q = u & 3;
            int gr = row0 + row;
            bool ok = gr < M;
            const __nv_bfloat16* pH = ok ? (Ahi + (size_t)gr * KTOT + kc + q * 8) : Ahi;
            const __nv_bfloat16* pL = ok ? (Alo + (size_t)gr * KTOT + kc + q * 8) : Alo;
            cp16p((uint32_t)__cvta_generic_to_shared(base + ST_AH + row * LDSW + q * 8), pH, ok);
            cp16p((uint32_t)__cvta_generic_to_shared(base + ST_AL + row * LDSW + q * 8), pL, ok);
        }
        {
            int u = tid;
            if (u < 256) {
                int row = u >> 2, q = u & 3;
                int gn = col0 + row;
                cp16p((uint32_t)__cvta_generic_to_shared(base + ST_BH + row * LDSW + q * 8),
                      Bhi + (size_t)gn * KTOT + kc + q * 8, true);
                cp16p((uint32_t)__cvta_generic_to_shared(base + ST_BL + row * LDSW + q * 8),
                      Blo + (size_t)gn * KTOT + kc + q * 8, true);
            }
        }
        asm volatile("cp.async.commit_group;" ::: "memory");
    };

    issue(0, 0);

    for (int c = 0; c < NCH; c++) {
        int s = c & 1;
        if (c + 1 < NCH) {
            issue(c + 1, (c + 1) & 1);
            asm volatile("cp.async.wait_group 1;" ::: "memory");
        } else {
            asm volatile("cp.async.wait_group 0;" ::: "memory");
        }
        __syncthreads();

        const __nv_bfloat16* base = smem + s * STAGE;
        const __nv_bfloat16* asH = base + ST_AH;
        const __nv_bfloat16* asL = base + ST_AL;
        const __nv_bfloat16* bsH = base + ST_BH;
        const __nv_bfloat16* bsL = base + ST_BL;

        #pragma unroll
        for (int ko = 0; ko < BK; ko += 16) {
            uint32_t ah[2][4], al[2][4];
            #pragma unroll
            for (int mt = 0; mt < 2; mt++) {
                int rb = wm * 32 + mt * 16;
                ah[mt][0] = *reinterpret_cast<const uint32_t*>(asH + (rb + g    ) * LDSW + ko + t2    );
                ah[mt][1] = *reinterpret_cast<const uint32_t*>(asH + (rb + g + 8) * LDSW + ko + t2    );
                ah[mt][2] = *reinterpret_cast<const uint32_t*>(asH + (rb + g    ) * LDSW + ko + t2 + 8);
                ah[mt][3] = *reinterpret_cast<const uint32_t*>(asH + (rb + g + 8) * LDSW + ko + t2 + 8);
                al[mt][0] = *reinterpret_cast<const uint32_t*>(asL + (rb + g    ) * LDSW + ko + t2    );
                al[mt][1] = *reinterpret_cast<const uint32_t*>(asL + (rb + g + 8) * LDSW + ko + t2    );
                al[mt][2] = *reinterpret_cast<const uint32_t*>(asL + (rb + g    ) * LDSW + ko + t2 + 8);
                al[mt][3] = *reinterpret_cast<const uint32_t*>(asL + (rb + g + 8) * LDSW + ko + t2 + 8);
            }
            uint32_t bh[NT][2], bl[NT][2];
            #pragma unroll
            for (int nt = 0; nt < NT; nt++) {
                int nb = wn * 32 + nt * 8 + g;
                bh[nt][0] = *reinterpret_cast<const uint32_t*>(bsH + nb * LDSW + ko + t2    );
                bh[nt][1] = *reinterpret_cast<const uint32_t*>(bsH + nb * LDSW + ko + t2 + 8);
                bl[nt][0] = *reinterpret_cast<const uint32_t*>(bsL + nb * LDSW + ko + t2    );
                bl[nt][1] = *reinterpret_cast<const uint32_t*>(bsL + nb * LDSW + ko + t2 + 8);
            }
            #pragma unroll
            for (int mt = 0; mt < 2; mt++)
                #pragma unroll
                for (int nt = 0; nt < NT; nt++) {
                    mma16816(acc[mt][nt], ah[mt], bh[nt]);
                    mma16816(acc[mt][nt], ah[mt], bl[nt]);
                    mma16816(acc[mt][nt], al[mt], bh[nt]);
                }
        }
        __syncthreads();
    }

    #pragma unroll
    for (int mt = 0; mt < 2; mt++) {
        int rbase = row0 + wm * 32 + mt * 16;
        #pragma unroll
        for (int half = 0; half < 2; half++) {
            int r = rbase + g + half * 8;
            if (r >= M) continue;
            #pragma unroll
            for (int nt = 0; nt < NT; nt++) {
                int c = col0 + wn * 32 + nt * 8 + t2;
                float v0 = acc[mt][nt][half * 2 + 0];
                float v1 = acc[mt][nt][half * 2 + 1];
                if (EPI != 1) { v0 += bias[c]; v1 += bias[c + 1]; }
                if (EPI == 0) {
                    __nv_bfloat16 h0, l0, h1, l1;
                    split_bf16(v0, h0, l0);
                    split_bf16(v1, h1, l1);
                    __nv_bfloat162 ph; ph.x = h0; ph.y = h1;
                    __nv_bfloat162 pl; pl.x = l0; pl.y = l1;
                    *reinterpret_cast<__nv_bfloat162*>(&Chi[(size_t)r * Nout + c]) = ph;
                    *reinterpret_cast<__nv_bfloat162*>(&Clo[(size_t)r * Nout + c]) = pl;
                } else if (EPI == 1) {
                    *reinterpret_cast<__half2*>(&Chf[(size_t)r * Nout + c]) =
                        __floats2half2_rn(v0, v1);
                } else {
                    *reinterpret_cast<float2*>(&Cf[(size_t)r * Nout + c]) = make_float2(v0, v1);
                }
            }
        }
    }
}

// ---------------- fused gather aggregation (fp16 ht input) ----------------
__device__ __forceinline__ void hfma8(float* acc, uint4 v, float w) {
    const __half2* h = reinterpret_cast<const __half2*>(&v);
    #pragma unroll
    for (int z = 0; z < 4; z++) {
        float2 f = __half22float2(h[z]);
        acc[z * 2]     += f.x * w;
        acc[z * 2 + 1] += f.y * w;
    }
}

__global__ __launch_bounds__(256)
void k_gather(const __half* __restrict__ ht, const int2* __restrict__ csr,
              const int* __restrict__ rowptr, const float* __restrict__ dinv,
              const float* __restrict__ b,
              __nv_bfloat16* __restrict__ hhi, __nv_bfloat16* __restrict__ hlo, int n) {
    int warp = (blockIdx.x * blockDim.x + threadIdx.x) >> 5;
    int lane = threadIdx.x & 31;
    if (warp >= n) return;
    int i = warp;

    float di = dinv[i];
    float w0 = di * di;
    float acc[8] = {0.f, 0.f, 0.f, 0.f, 0.f, 0.f, 0.f, 0.f};

    // self term
    {
        uint4 v = reinterpret_cast<const uint4*>(ht + (size_t)i * DH)[lane];
        hfma8(acc, v, w0);
    }

    int beg = rowptr[i], end = rowptr[i + 1];
    int j = beg;
    for (; j + 1 < end; j += 2) {
        int2 e0 = csr[j], e1 = csr[j + 1];
        uint4 v0 = reinterpret_cast<const uint4*>(ht + (size_t)e0.x * DH)[lane];
        uint4 v1 = reinterpret_cast<const uint4*>(ht + (size_t)e1.x * DH)[lane];
        hfma8(acc, v0, __int_as_float(e0.y));
        hfma8(acc, v1, __int_as_float(e1.y));
    }
    if (j < end) {
        int2 e0 = csr[j];
        uint4 v0 = reinterpret_cast<const uint4*>(ht + (size_t)e0.x * DH)[lane];
        hfma8(acc, v0, __int_as_float(e0.y));
    }

    const float4* bp = reinterpret_cast<const float4*>(b);
    float4 b0 = bp[lane * 2], b1 = bp[lane * 2 + 1];
    float bb[8] = { b0.x, b0.y, b0.z, b0.w, b1.x, b1.y, b1.z, b1.w };

    __nv_bfloat16 hh[8], ll[8];
    #pragma unroll
    for (int q = 0; q < 8; q++) {
        float v = tanhf(acc[q] + bb[q]);
        split_bf16(v, hh[q], ll[q]);
    }
    *reinterpret_cast<uint4*>(hhi + (size_t)i * DH + lane * 8) = *reinterpret_cast<uint4*>(hh);
    *reinterpret_cast<uint4*>(hlo + (size_t)i * DH + lane * 8) = *reinterpret_cast<uint4*>(ll);
}

// ---------------- launcher ----------------
extern "C" void kernel_launch(void* const* d_in, const int* in_sizes, int n_in,
                              void* d_out, int out_size) {
    const float* x      = (const float*)d_in[0];
    const int*   eidx   = (const int*)  d_in[1];
    const float* W_emb  = (const float*)d_in[2];
    const float* b_emb  = (const float*)d_in[3];
    const float* W_conv = (const float*)d_in[4];
    const float* b_conv = (const float*)d_in[5];
    const float* W_out  = (const float*)d_in[6];
    const float* b_out  = (const float*)d_in[7];
    float* out = (float*)d_out;

    int E = in_sizes[1] / 2;
    if (E > E_MAX) E = E_MAX;
    const int* src = eidx;
    const int* dst = eidx + E;
    const int n = N_NODES;

    float *dinv;
    __half *ht;
    int *cnt, *partial, *rowptr, *cursor;
    int2 *csr;
    __nv_bfloat16 *xhi, *xlo, *hhi, *hlo;
    __nv_bfloat16 *wembh, *wembl, *wconvh, *wconvl, *wouth, *woutl;
    cudaGetSymbolAddress((void**)&dinv,   g_dinv);
    cudaGetSymbolAddress((void**)&cnt,    g_cnt);
    cudaGetSymbolAddress((void**)&partial,g_partial);
    cudaGetSymbolAddress((void**)&rowptr, g_rowptr);
    cudaGetSymbolAddress((void**)&cursor, g_cursor);
    cudaGetSymbolAddress((void**)&csr,    g_csr);
    cudaGetSymbolAddress((void**)&ht,   g_ht);
    cudaGetSymbolAddress((void**)&xhi,  g_xhi);
    cudaGetSymbolAddress((void**)&xlo,  g_xlo);
    cudaGetSymbolAddress((void**)&hhi,  g_hhi);
    cudaGetSymbolAddress((void**)&hlo,  g_hlo);
    cudaGetSymbolAddress((void**)&wembh, g_wembh);
    cudaGetSymbolAddress((void**)&wembl, g_wembl);
    cudaGetSymbolAddress((void**)&wconvh, g_wconvh);
    cudaGetSymbolAddress((void**)&wconvl, g_wconvl);
    cudaGetSymbolAddress((void**)&wouth, g_wouth);
    cudaGetSymbolAddress((void**)&woutl, g_woutl);

    const int SMEM_GEMM = 2 * STAGE * (int)sizeof(__nv_bfloat16);   // 61440
    cudaFuncSetAttribute(k_mma_gemm<DIN, 0>, cudaFuncAttributeMaxDynamicSharedMemorySize, SMEM_GEMM);
    cudaFuncSetAttribute(k_mma_gemm<DH, 1>,  cudaFuncAttributeMaxDynamicSharedMemorySize, SMEM_GEMM);
    cudaFuncSetAttribute(k_mma_gemm<DH, 2>,  cudaFuncAttributeMaxDynamicSharedMemorySize, SMEM_GEMM);

    // CSR build + dinv
    k_zero <<<(n + 255) / 256, 256>>>(cnt, n);
    k_count<<<(E + 255) / 256, 256>>>(dst, cnt, E);
    k_dinv <<<(n + 255) / 256, 256>>>(cnt, dinv, n);
    k_scan1<<<SCAN_NB, 256>>>(cnt, partial, n);
    k_scan2<<<1, 64>>>(partial, rowptr, SCAN_NB, n);
    k_scan3<<<SCAN_NB, 256>>>(cnt, partial, rowptr, cursor, n);
    k_fill <<<(E + 255) / 256, 256>>>(src, dst, dinv, cursor, csr, E);

    // conversions
    k_conv_x<<<(n * DIN + 255) / 256, 256>>>(x, xhi, xlo, n * DIN);
    k_conv_w<<<(DIN * DH + 255) / 256, 256>>>(W_emb, wembh, wembl, DIN, DH);
    k_conv_wall<<<(LAYERS * DH * DH + 255) / 256, 256>>>(W_conv, wconvh, wconvl);
    k_conv_w<<<(DH * DOUT + 255) / 256, 256>>>(W_out, wouth, woutl, DH, DOUT);

    int gy = (n + 127) / 128;

    // embedding: h = x @ W_emb + b_emb -> bf16 split
    {
        dim3 grid(DH / 64, gy);
        k_mma_gemm<DIN, 0><<<grid, 256, SMEM_GEMM>>>(xhi, xlo, wembh, wembl, b_emb,
                                                     nullptr, nullptr, hhi, hlo, n, DH);
    }

    int gather_blocks = (n * 32 + 255) / 256;
    for (int l = 0; l < LAYERS; l++) {
        const float* b = b_conv + (size_t)l * DH;
        dim3 grid(DH / 64, gy);
        k_mma_gemm<DH, 1><<<grid, 256, SMEM_GEMM>>>(hhi, hlo,
                                                    wconvh + (size_t)l * DH * DH,
                                                    wconvl + (size_t)l * DH * DH,
                                                    nullptr, nullptr, ht, nullptr, nullptr, n, DH);
        k_gather<<<gather_blocks, 256>>>(ht, csr, rowptr, dinv, b, hhi, hlo, n);
    }

    // output: out = h @ W_out + b_out
    {
        dim3 grid(DOUT / 64, gy);
        k_mma_gemm<DH, 2><<<grid, 256, SMEM_GEMM>>>(hhi, hlo, wouth, woutl, b_out,
                                                    out, nullptr, nullptr, nullptr, n, DOUT);
    }
}

// round 16
// speedup vs baseline: 2.1346x; 1.2507x over previous
#include <cuda_runtime.h>
#include <cuda_bf16.h>
#include <cuda_fp16.h>
#include <cstdint>
#include <math.h>

#define N_NODES 50000
#define E_MAX   800000
#define DIN     128
#define DH      256
#define DOUT    64
#define LAYERS  4

#define SCAN_NB  ((N_NODES + 1023) / 1024)   // 49

// ---------------- device scratch (allocation-free) ----------------
__device__ float g_dinv[N_NODES];
__device__ int   g_cnt[N_NODES];
__device__ int   g_partial[64];
__device__ int   g_rowptr[N_NODES + 1];
__device__ int   g_cursor[N_NODES];
__device__ int2  g_csr[E_MAX];                    // {src, norm-as-int}
__device__ __half g_x [(size_t)N_NODES * DIN];    // fp16 input features
__device__ __half g_h [(size_t)N_NODES * DH];     // fp16 activations
__device__ __half g_ht[(size_t)N_NODES * DH];     // fp16 pre-activation (gather path)
// transposed fp16 weights [N][K] (K-major rows), hi/lo split
__device__ __half g_wembh[DH * DIN], g_wembl[DH * DIN];
__device__ __half g_wconvh[LAYERS * DH * DH], g_wconvl[LAYERS * DH * DH];
__device__ __half g_wouth[DOUT * DH], g_woutl[DOUT * DH];

// ---------------- CSR build ----------------
__global__ void k_zero(int* cnt, int n) {
    int i = blockIdx.x * blockDim.x + threadIdx.x;
    if (i < n) cnt[i] = 0;
}
__global__ void k_count(const int* __restrict__ dst, int* cnt, int E) {
    int e = blockIdx.x * blockDim.x + threadIdx.x;
    if (e < E) atomicAdd(&cnt[dst[e]], 1);
}
__global__ void k_dinv(const int* __restrict__ cnt, float* dinv, int n) {
    int i = blockIdx.x * blockDim.x + threadIdx.x;
    if (i < n) dinv[i] = rsqrtf((float)cnt[i] + 1.0f);   // +1 self-loop
}
__global__ void k_scan1(const int* __restrict__ cnt, int* partial, int n) {
    __shared__ int sd[256];
    int base = blockIdx.x * 1024;
    int t = threadIdx.x;
    int s = 0;
    #pragma unroll
    for (int i = 0; i < 4; i++) {
        int idx = base + t + i * 256;
        if (idx < n) s += cnt[idx];
    }
    sd[t] = s;
    __syncthreads();
    #pragma unroll
    for (int off = 128; off > 0; off >>= 1) {
        if (t < off) sd[t] += sd[t + off];
        __syncthreads();
    }
    if (t == 0) partial[blockIdx.x] = sd[0];
}
__global__ void k_scan2(int* partial, int* rowptr, int nb, int n) {
    __shared__ int sh[64];
    int t = threadIdx.x;
    int v = (t < nb) ? partial[t] : 0;
    sh[t] = v;
    __syncthreads();
    #pragma unroll
    for (int off = 1; off < 64; off <<= 1) {
        int x = (t >= off) ? sh[t - off] : 0;
        __syncthreads();
        sh[t] += x;
        __syncthreads();
    }
    if (t < nb) partial[t] = sh[t] - v;      // exclusive
    if (t == 63) rowptr[n] = sh[63];
}
__global__ void k_scan3(const int* __restrict__ cnt, const int* __restrict__ partial,
                        int* rowptr, int* cursor, int n) {
    __shared__ int sh[256];
    int base = blockIdx.x * 1024;
    int t = threadIdx.x;
    int i0 = base + t * 4;
    int c0 = (i0     < n) ? cnt[i0    ] : 0;
    int c1 = (i0 + 1 < n) ? cnt[i0 + 1] : 0;
    int c2 = (i0 + 2 < n) ? cnt[i0 + 2] : 0;
    int c3 = (i0 + 3 < n) ? cnt[i0 + 3] : 0;
    int tot = c0 + c1 + c2 + c3;
    sh[t] = tot;
    __syncthreads();
    #pragma unroll
    for (int off = 1; off < 256; off <<= 1) {
        int x = (t >= off) ? sh[t - off] : 0;
        __syncthreads();
        sh[t] += x;
        __syncthreads();
    }
    int run = sh[t] - tot + partial[blockIdx.x];
    if (i0     < n) { rowptr[i0    ] = run; cursor[i0    ] = run; run += c0; }
    if (i0 + 1 < n) { rowptr[i0 + 1] = run; cursor[i0 + 1] = run; run += c1; }
    if (i0 + 2 < n) { rowptr[i0 + 2] = run; cursor[i0 + 2] = run; run += c2; }
    if (i0 + 3 < n) { rowptr[i0 + 3] = run; cursor[i0 + 3] = run; }
}
__global__ void k_fill(const int* __restrict__ src, const int* __restrict__ dst,
                       const float* __restrict__ dinv, int* cursor,
                       int2* __restrict__ csr, int E) {
    int e = blockIdx.x * blockDim.x + threadIdx.x;
    if (e >= E) return;
    int s = src[e], d = dst[e];
    int pos = atomicAdd(&cursor[d], 1);
    float w = dinv[s] * dinv[d];
    csr[pos] = make_int2(s, __float_as_int(w));
}

// ---------------- conversions ----------------
__device__ __forceinline__ void split_fp16(float v, __half& hi, __half& lo) {
    hi = __float2half_rn(v);
    lo = __float2half_rn(v - __half2float(hi));
}
__global__ void k_conv_x(const float* __restrict__ x, __half* __restrict__ out, int total) {
    int i = blockIdx.x * blockDim.x + threadIdx.x;
    if (i >= total) return;
    out[i] = __float2half_rn(x[i]);
}
// W [K][N] fp32 -> out [N][K] fp16 hi/lo
__global__ void k_conv_w(const float* __restrict__ W,
                         __half* __restrict__ hi, __half* __restrict__ lo,
                         int K, int N) {
    int i = blockIdx.x * blockDim.x + threadIdx.x;
    if (i >= K * N) return;
    int k = i / N, n = i % N;
    __half h, l;
    split_fp16(W[i], h, l);
    hi[(size_t)n * K + k] = h;
    lo[(size_t)n * K + k] = l;
}
// all conv layers in one launch
__global__ void k_conv_wall(const float* __restrict__ W,
                            __half* __restrict__ hi, __half* __restrict__ lo) {
    int i = blockIdx.x * blockDim.x + threadIdx.x;
    if (i >= LAYERS * DH * DH) return;
    int l = i / (DH * DH);
    int r = i % (DH * DH);
    int k = r / DH, n = r % DH;
    __half h, lw;
    split_fp16(W[i], h, lw);
    size_t o = (size_t)l * DH * DH + (size_t)n * DH + k;
    hi[o] = h;
    lo[o] = lw;
}

// ---------------- mma.sync fp16 GEMM, 2-term (A*Whi + A*Wlo), cp.async 2-stage ----------------
__device__ __forceinline__ void mma16816(float* c, const uint32_t* a, const uint32_t* b) {
    asm volatile(
        "mma.sync.aligned.m16n8k16.row.col.f32.f16.f16.f32 "
        "{%0,%1,%2,%3}, {%4,%5,%6,%7}, {%8,%9}, {%0,%1,%2,%3};"
        : "+f"(c[0]), "+f"(c[1]), "+f"(c[2]), "+f"(c[3])
        : "r"(a[0]), "r"(a[1]), "r"(a[2]), "r"(a[3]), "r"(b[0]), "r"(b[1]));
}
__device__ __forceinline__ void cp16p(uint32_t dst, const void* src, bool valid) {
    int sz = valid ? 16 : 0;
    asm volatile("cp.async.cg.shared.global [%0], [%1], 16, %2;"
                 :: "r"(dst), "l"(src), "r"(sz) : "memory");
}

// smem layout per stage (fp16 elements): As[128*40] BsH[64*40] BsL[64*40]
#define LDSW  40
#define ST_A  0
#define ST_BH (128 * LDSW)
#define ST_BL (128 * LDSW + 64 * LDSW)
#define STAGE (128 * LDSW + 2 * 64 * LDSW)   // 10240 elements

// EPI: 0 = bias + fp16 out (emb h), 1 = fp16 out no bias (conv ht), 2 = bias + fp32 (out)
template<int KTOT, int EPI>
__global__ __launch_bounds__(256)
void k_mma_gemm(const __half* __restrict__ A,
                const __half* __restrict__ Bhi, const __half* __restrict__ Blo,
                const float* __restrict__ bias,
                float* __restrict__ Cf, __half* __restrict__ Chf,
                int M, int Nout) {
    constexpr int BK = 32, NT = 4;
    constexpr int NCH = KTOT / BK;
    extern __shared__ char smem_raw[];
    __half* smem = reinterpret_cast<__half*>(smem_raw);

    int tid = threadIdx.x;
    int lane = tid & 31, wid = tid >> 5;
    int wm = wid & 3, wn = wid >> 2;
    int g = lane >> 2, t2 = (lane & 3) * 2;

    int row0 = blockIdx.y * 128;
    int col0 = blockIdx.x * 64;

    float acc[2][NT][4];
    #pragma unroll
    for (int mt = 0; mt < 2; mt++)
        #pragma unroll
        for (int nt = 0; nt < NT; nt++)
            #pragma unroll
            for (int j = 0; j < 4; j++) acc[mt][nt][j] = 0.f;

    // async load of chunk kc into stage s
    auto issue = [&](int c, int s) {
        int kc = c * BK;
        __half* base = smem + s * STAGE;
        // A: 128 rows x 32 fp16 = 512 uint4
        #pragma unroll
        for (int u = tid; u < 512; u += 256) {
            int row = u >> 2, q = u & 3;
            int gr = row0 + row;
            bool ok = gr < M;
            const __half* pA = ok ? (A + (size_t)gr * KTOT + kc + q * 8) : A;
            cp16p((uint32_t)__cvta_generic_to_shared(base + ST_A + row * LDSW + q * 8), pA, ok);
        }
        // B: 64 rows x 32 fp16 (hi + lo) = 256+256 uint4
        {
            int u = tid;
            if (u < 256) {
                int row = u >> 2, q = u & 3;
                int gn = col0 + row;
                cp16p((uint32_t)__cvta_generic_to_shared(base + ST_BH + row * LDSW + q * 8),
                      Bhi + (size_t)gn * KTOT + kc + q * 8, true);
                cp16p((uint32_t)__cvta_generic_to_shared(base + ST_BL + row * LDSW + q * 8),
                      Blo + (size_t)gn * KTOT + kc + q * 8, true);
            }
        }
        asm volatile("cp.async.commit_group;" ::: "memory");
    };

    issue(0, 0);

    for (int c = 0; c < NCH; c++) {
        int s = c & 1;
        if (c + 1 < NCH) {
            issue(c + 1, (c + 1) & 1);
            asm volatile("cp.async.wait_group 1;" ::: "memory");
        } else {
            asm volatile("cp.async.wait_group 0;" ::: "memory");
        }
        __syncthreads();

        const __half* base = smem + s * STAGE;
        const __half* as  = base + ST_A;
        const __half* bsH = base + ST_BH;
        const __half* bsL = base + ST_BL;

        #pragma unroll
        for (int ko = 0; ko < BK; ko += 16) {
            uint32_t a[2][4];
            #pragma unroll
            for (int mt = 0; mt < 2; mt++) {
                int rb = wm * 32 + mt * 16;
                a[mt][0] = *reinterpret_cast<const uint32_t*>(as + (rb + g    ) * LDSW + ko + t2    );
                a[mt][1] = *reinterpret_cast<const uint32_t*>(as + (rb + g + 8) * LDSW + ko + t2    );
                a[mt][2] = *reinterpret_cast<const uint32_t*>(as + (rb + g    ) * LDSW + ko + t2 + 8);
                a[mt][3] = *reinterpret_cast<const uint32_t*>(as + (rb + g + 8) * LDSW + ko + t2 + 8);
            }
            uint32_t bh[NT][2], bl[NT][2];
            #pragma unroll
            for (int nt = 0; nt < NT; nt++) {
                int nb = wn * 32 + nt * 8 + g;
                bh[nt][0] = *reinterpret_cast<const uint32_t*>(bsH + nb * LDSW + ko + t2    );
                bh[nt][1] = *reinterpret_cast<const uint32_t*>(bsH + nb * LDSW + ko + t2 + 8);
                bl[nt][0] = *reinterpret_cast<const uint32_t*>(bsL + nb * LDSW + ko + t2    );
                bl[nt][1] = *reinterpret_cast<const uint32_t*>(bsL + nb * LDSW + ko + t2 + 8);
            }
            #pragma unroll
            for (int mt = 0; mt < 2; mt++)
                #pragma unroll
                for (int nt = 0; nt < NT; nt++) {
                    mma16816(acc[mt][nt], a[mt], bh[nt]);
                    mma16816(acc[mt][nt], a[mt], bl[nt]);
                }
        }
        __syncthreads();
    }

    #pragma unroll
    for (int mt = 0; mt < 2; mt++) {
        int rbase = row0 + wm * 32 + mt * 16;
        #pragma unroll
        for (int half = 0; half < 2; half++) {
            int r = rbase + g + half * 8;
            if (r >= M) continue;
            #pragma unroll
            for (int nt = 0; nt < NT; nt++) {
                int c = col0 + wn * 32 + nt * 8 + t2;
                float v0 = acc[mt][nt][half * 2 + 0];
                float v1 = acc[mt][nt][half * 2 + 1];
                if (EPI != 1) { v0 += bias[c]; v1 += bias[c + 1]; }
                if (EPI == 2) {
                    *reinterpret_cast<float2*>(&Cf[(size_t)r * Nout + c]) = make_float2(v0, v1);
                } else {
                    *reinterpret_cast<__half2*>(&Chf[(size_t)r * Nout + c]) =
                        __floats2half2_rn(v0, v1);
                }
            }
        }
    }
}

// ---------------- fused gather aggregation (fp16 in, fp16 out) ----------------
__device__ __forceinline__ void hfma8(float* acc, uint4 v, float w) {
    const __half2* h = reinterpret_cast<const __half2*>(&v);
    #pragma unroll
    for (int z = 0; z < 4; z++) {
        float2 f = __half22float2(h[z]);
        acc[z * 2]     += f.x * w;
        acc[z * 2 + 1] += f.y * w;
    }
}

__global__ __launch_bounds__(256)
void k_gather(const __half* __restrict__ ht, const int2* __restrict__ csr,
              const int* __restrict__ rowptr, const float* __restrict__ dinv,
              const float* __restrict__ b,
              __half* __restrict__ hout, int n) {
    int warp = (blockIdx.x * blockDim.x + threadIdx.x) >> 5;
    int lane = threadIdx.x & 31;
    if (warp >= n) return;
    int i = warp;

    float di = dinv[i];
    float w0 = di * di;
    float acc[8] = {0.f, 0.f, 0.f, 0.f, 0.f, 0.f, 0.f, 0.f};

    // self term
    {
        uint4 v = reinterpret_cast<const uint4*>(ht + (size_t)i * DH)[lane];
        hfma8(acc, v, w0);
    }

    int beg = rowptr[i], end = rowptr[i + 1];
    int j = beg;
    for (; j + 1 < end; j += 2) {
        int2 e0 = csr[j], e1 = csr[j + 1];
        uint4 v0 = reinterpret_cast<const uint4*>(ht + (size_t)e0.x * DH)[lane];
        uint4 v1 = reinterpret_cast<const uint4*>(ht + (size_t)e1.x * DH)[lane];
        hfma8(acc, v0, __int_as_float(e0.y));
        hfma8(acc, v1, __int_as_float(e1.y));
    }
    if (j < end) {
        int2 e0 = csr[j];
        uint4 v0 = reinterpret_cast<const uint4*>(ht + (size_t)e0.x * DH)[lane];
        hfma8(acc, v0, __int_as_float(e0.y));
    }

    const float4* bp = reinterpret_cast<const float4*>(b);
    float4 b0 = bp[lane * 2], b1 = bp[lane * 2 + 1];
    float bb[8] = { b0.x, b0.y, b0.z, b0.w, b1.x, b1.y, b1.z, b1.w };

    __half hh[8];
    #pragma unroll
    for (int q = 0; q < 8; q++)
        hh[q] = __float2half_rn(tanhf(acc[q] + bb[q]));
    *reinterpret_cast<uint4*>(hout + (size_t)i * DH + lane * 8) = *reinterpret_cast<uint4*>(hh);
}

// ---------------- launcher ----------------
extern "C" void kernel_launch(void* const* d_in, const int* in_sizes, int n_in,
                              void* d_out, int out_size) {
    const float* x      = (const float*)d_in[0];
    const int*   eidx   = (const int*)  d_in[1];
    const float* W_emb  = (const float*)d_in[2];
    const float* b_emb  = (const float*)d_in[3];
    const float* W_conv = (const float*)d_in[4];
    const float* b_conv = (const float*)d_in[5];
    const float* W_out  = (const float*)d_in[6];
    const float* b_out  = (const float*)d_in[7];
    float* out = (float*)d_out;

    int E = in_sizes[1] / 2;
    if (E > E_MAX) E = E_MAX;
    const int* src = eidx;
    const int* dst = eidx + E;
    const int n = N_NODES;

    float *dinv;
    __half *xh, *h, *ht;
    int *cnt, *partial, *rowptr, *cursor;
    int2 *csr;
    __half *wembh, *wembl, *wconvh, *wconvl, *wouth, *woutl;
    cudaGetSymbolAddress((void**)&dinv,   g_dinv);
    cudaGetSymbolAddress((void**)&cnt,    g_cnt);
    cudaGetSymbolAddress((void**)&partial,g_partial);
    cudaGetSymbolAddress((void**)&rowptr, g_rowptr);
    cudaGetSymbolAddress((void**)&cursor, g_cursor);
    cudaGetSymbolAddress((void**)&csr,    g_csr);
    cudaGetSymbolAddress((void**)&xh,   g_x);
    cudaGetSymbolAddress((void**)&h,    g_h);
    cudaGetSymbolAddress((void**)&ht,   g_ht);
    cudaGetSymbolAddress((void**)&wembh, g_wembh);
    cudaGetSymbolAddress((void**)&wembl, g_wembl);
    cudaGetSymbolAddress((void**)&wconvh, g_wconvh);
    cudaGetSymbolAddress((void**)&wconvl, g_wconvl);
    cudaGetSymbolAddress((void**)&wouth, g_wouth);
    cudaGetSymbolAddress((void**)&woutl, g_woutl);

    const int SMEM_GEMM = 2 * STAGE * (int)sizeof(__half);   // 40960
    cudaFuncSetAttribute(k_mma_gemm<DIN, 0>, cudaFuncAttributeMaxDynamicSharedMemorySize, SMEM_GEMM);
    cudaFuncSetAttribute(k_mma_gemm<DH, 1>,  cudaFuncAttributeMaxDynamicSharedMemorySize, SMEM_GEMM);
    cudaFuncSetAttribute(k_mma_gemm<DH, 2>,  cudaFuncAttributeMaxDynamicSharedMemorySize, SMEM_GEMM);

    // CSR build + dinv
    k_zero <<<(n + 255) / 256, 256>>>(cnt, n);
    k_count<<<(E + 255) / 256, 256>>>(dst, cnt, E);
    k_dinv <<<(n + 255) / 256, 256>>>(cnt, dinv, n);
    k_scan1<<<SCAN_NB, 256>>>(cnt, partial, n);
    k_scan2<<<1, 64>>>(partial, rowptr, SCAN_NB, n);
    k_scan3<<<SCAN_NB, 256>>>(cnt, partial, rowptr, cursor, n);
    k_fill <<<(E + 255) / 256, 256>>>(src, dst, dinv, cursor, csr, E);

    // conversions
    k_conv_x<<<(n * DIN + 255) / 256, 256>>>(x, xh, n * DIN);
    k_conv_w<<<(DIN * DH + 255) / 256, 256>>>(W_emb, wembh, wembl, DIN, DH);
    k_conv_wall<<<(LAYERS * DH * DH + 255) / 256, 256>>>(W_conv, wconvh, wconvl);
    k_conv_w<<<(DH * DOUT + 255) / 256, 256>>>(W_out, wouth, woutl, DH, DOUT);

    int gy = (n + 127) / 128;

    // embedding: h = x @ W_emb + b_emb -> fp16
    {
        dim3 grid(DH / 64, gy);
        k_mma_gemm<DIN, 0><<<grid, 256, SMEM_GEMM>>>(xh, wembh, wembl, b_emb,
                                                     nullptr, h, n, DH);
    }

    int gather_blocks = (n * 32 + 255) / 256;
    for (int l = 0; l < LAYERS; l++) {
        const float* b = b_conv + (size_t)l * DH;
        dim3 grid(DH / 64, gy);
        k_mma_gemm<DH, 1><<<grid, 256, SMEM_GEMM>>>(h,
                                                    wconvh + (size_t)l * DH * DH,
                                                    wconvl + (size_t)l * DH * DH,
                                                    nullptr, nullptr, ht, n, DH);
        k_gather<<<gather_blocks, 256>>>(ht, csr, rowptr, dinv, b, h, n);
    }

    // output: out = h @ W_out + b_out
    {
        dim3 grid(DOUT / 64, gy);
        k_mma_gemm<DH, 2><<<grid, 256, SMEM_GEMM>>>(h, wouth, woutl, b_out,
                                                    out, nullptr, n, DOUT);
    }
}